// round 11
// baseline (speedup 1.0000x reference)
#include <cuda_runtime.h>
#include <cuda_bf16.h>
#include <cstdint>

#define HWSZ 9216
#define IMG  96
typedef __nv_bfloat16 bf16;

// ---------------- device scratch ----------------
__device__ bf16 g_xh[2 * HWSZ * 2048];
__device__ bf16 g_xl[2 * HWSZ * 2048];
__device__ bf16 g_zh[2 * HWSZ * 512];
__device__ bf16 g_zl[2 * HWSZ * 512];
__device__ float g_z   [2 * HWSZ * 512];
__device__ float g_z2  [2 * HWSZ * 512];
__device__ float g_qkv [2 * HWSZ * 640];   // [q 0:64 | k 64:128 | v 128:640]
__device__ float g_attn[2 * HWSZ * 192];
__device__ float g_acc [2 * HWSZ * 512];
__device__ float g_cl  [2 * HWSZ * 512];
__device__ bf16 g_c1h[512 * 2048], g_c1l[512 * 2048];
__device__ bf16 g_qvh[640 * 512],  g_qvl[640 * 512];
__device__ bf16 g_w9h[9 * 512 * 512], g_w9l[9 * 512 * 512];
__device__ float g_bqv[640];
__device__ float g_stat[128];

// ---------------- helpers ----------------
__device__ __forceinline__ uint32_t s2u(const void* p) {
    uint32_t a;
    asm("{ .reg .u64 t; cvta.to.shared.u64 t, %1; cvt.u32.u64 %0, t; }" : "=r"(a) : "l"(p));
    return a;
}
__device__ __forceinline__ void bsplit(float v, bf16* h, bf16* l) {
    bf16 hh = __float2bfloat16(v);
    *h = hh;
    *l = __float2bfloat16(v - __bfloat162float(hh));
}
__device__ __forceinline__ void mma16816(float* d, const uint32_t* a, const uint32_t* b) {
    asm volatile(
        "mma.sync.aligned.m16n8k16.row.col.f32.bf16.bf16.f32 "
        "{%0,%1,%2,%3}, {%4,%5,%6,%7}, {%8,%9}, {%0,%1,%2,%3};"
        : "+f"(d[0]), "+f"(d[1]), "+f"(d[2]), "+f"(d[3])
        : "r"(a[0]), "r"(a[1]), "r"(a[2]), "r"(a[3]), "r"(b[0]), "r"(b[1]));
}
__device__ __forceinline__ void cpasync16(uint32_t s, const void* g) {
    asm volatile("cp.async.cg.shared.global [%0], [%1], 16;" :: "r"(s), "l"(g));
}
__device__ __forceinline__ void ldm_x4(uint32_t* r, uint32_t addr) {
    asm volatile("ldmatrix.sync.aligned.m8n8.x4.shared.b16 {%0,%1,%2,%3}, [%4];"
                 : "=r"(r[0]), "=r"(r[1]), "=r"(r[2]), "=r"(r[3]) : "r"(addr));
}

// ---------------- packing / splitting ----------------
__global__ void split_x(const float* __restrict__ x, bf16* __restrict__ xh,
                        bf16* __restrict__ xl) {
    __shared__ float t[32][33];
    const int p0 = blockIdx.x * 32, c0 = blockIdx.y * 32, b = blockIdx.z;
    const int tx = threadIdx.x & 31, ty = threadIdx.x >> 5;
#pragma unroll
    for (int k = 0; k < 4; k++) {
        int cc = ty + k * 8;
        t[cc][tx] = x[((size_t)b * 2048 + c0 + cc) * HWSZ + p0 + tx];
    }
    __syncthreads();
#pragma unroll
    for (int k = 0; k < 4; k++) {
        int pl = ty + k * 8;
        float v = t[tx][pl];
        size_t o = ((size_t)b * HWSZ + p0 + pl) * 2048 + c0 + tx;
        bsplit(v, &xh[o], &xl[o]);
    }
}

// all weight splits in ONE kernel (keeps launch index of GEMMs low for ncu)
#define C1SZ  (512 * 2048)
#define QVSZ  (640 * 512)
#define W9SZ  (9 * 512 * 512)
__global__ void split_weights(const float* __restrict__ c1w,
                              const float* __restrict__ qw, const float* __restrict__ kw,
                              const float* __restrict__ vw, const float* __restrict__ qb,
                              const float* __restrict__ kb, const float* __restrict__ vb,
                              const float* __restrict__ cow,
                              bf16* __restrict__ c1h, bf16* __restrict__ c1l,
                              bf16* __restrict__ qvh, bf16* __restrict__ qvl,
                              bf16* __restrict__ w9h, bf16* __restrict__ w9l,
                              float* __restrict__ bqv) {
    int i = blockIdx.x * 256 + threadIdx.x;
    if (i < 640)
        bqv[i] = (i < 64) ? qb[i] : (i < 128) ? kb[i - 64] : vb[i - 128];
    if (i < C1SZ) {
        bsplit(c1w[i], &c1h[i], &c1l[i]);
    } else if (i < C1SZ + QVSZ) {
        int j = i - C1SZ;
        int m = j >> 9, k = j & 511;
        float v = (m < 64) ? qw[m * 512 + k]
                : (m < 128) ? kw[(m - 64) * 512 + k]
                            : vw[(m - 128) * 512 + k];
        bsplit(v, &qvh[j], &qvl[j]);
    } else if (i < C1SZ + QVSZ + W9SZ) {
        int d = i - C1SZ - QVSZ;
        int s = d / (512 * 512), r = d % (512 * 512);
        int o = r >> 9, ic = r & 511;
        bsplit(cow[(o * 512 + ic) * 9 + s], &w9h[d], &w9l[d]);
    }
}

// ---------------- bf16-split tensor-core GEMM (3-stage cp.async pipeline) --
// D[128 pix][128 ch] = A[pix][K].B[ch][K]^T via Ah*Bh + Ah*Bl + Al*Bh
// MODE 0: conv1 (fp32 + bf16 hi/lo out), 2: qkv, 3: conv3 (9 shifts)
#define OPSZ 5120            // elems per operand tile (128*40)
#define OPB  10240           // bytes per operand tile
#define BUFE 20480           // elems per stage buffer (4 operands)
#define BUFB 40960           // bytes per stage buffer
#define NSTG 3
#define MG_SMEM (4864 + NSTG * BUFB)
template <int MODE>
__global__ __launch_bounds__(256, 1)
void mma_gemm(const bf16* __restrict__ Ah, const bf16* __restrict__ Al,
              const bf16* __restrict__ Bh, const bf16* __restrict__ Bl,
              const float* __restrict__ bias, float* __restrict__ outf,
              bf16* __restrict__ oh, bf16* __restrict__ ol,
              int K, int Mtot)
{
    extern __shared__ char smem[];
    int* srcn = (int*)smem;
    bf16* tiles = (bf16*)(smem + 4864);
    const uint32_t smbase = s2u(tiles);
    const int tid = threadIdx.x, wid = tid >> 5, lane = tid & 31;
    const int n0 = blockIdx.x * 128, m0 = blockIdx.y * 128, b = blockIdx.z;

    if (MODE == 3 && tid < 128) {
        int n = n0 + tid, y = n / IMG, x = n - y * IMG;
#pragma unroll
        for (int s = 0; s < 9; s++) {
            int sy = y + s / 3 - 1, sx = x + s % 3 - 1;
            srcn[s * 128 + tid] = (sy >= 0 && sy < IMG && sx >= 0 && sx < IMG) ? sy * IMG + sx : -1;
        }
    }
    __syncthreads();

    const int g = tid >> 6, u = tid & 63, q = u & 3, rs = u >> 2;
    const bf16* srcp = (g == 0) ? Ah : (g == 1) ? Al : (g == 2) ? Bh : Bl;
    const int nch = (MODE == 3) ? 144 : (K >> 5);

    auto load_chunk = [&](int i) {
        bf16* t = tiles + (i % NSTG) * BUFE + g * OPSZ;
        int s = 0, k0;
        if (MODE == 3) { s = i >> 4; k0 = (i & 15) << 5; } else { k0 = i << 5; }
#pragma unroll
        for (int j = 0; j < 8; j++) {
            int row = rs + j * 16;
            uint32_t sa = s2u(t + row * 40 + q * 8);
            if (g < 2) {
                long rn = -1;
                if (MODE == 3) { int sn = srcn[s * 128 + row]; if (sn >= 0) rn = sn; }
                else rn = n0 + row;
                if (rn >= 0)
                    cpasync16(sa, srcp + ((size_t)b * HWSZ + rn) * (size_t)K + k0 + q * 8);
                else
                    *(uint4*)(t + row * 40 + q * 8) = make_uint4(0, 0, 0, 0);
            } else {
                size_t mrow = (MODE == 3) ? ((size_t)s * 512 + m0 + row) : (size_t)(m0 + row);
                cpasync16(sa, srcp + mrow * (size_t)K + k0 + q * 8);
            }
        }
        asm volatile("cp.async.commit_group;" ::: "memory");
    };

    float acc[4][4][4];
#pragma unroll
    for (int mi = 0; mi < 4; mi++)
#pragma unroll
        for (int ni = 0; ni < 4; ni++)
#pragma unroll
            for (int r = 0; r < 4; r++) acc[mi][ni][r] = 0.f;

    const int wm = wid >> 2, wn = wid & 3;
    const int lr = lane >> 2, lc = (lane & 3) * 2;
    const int mq = lane >> 3, rowin = lane & 7;

    uint32_t aoff[2][4], boff[2][2];
#pragma unroll
    for (int ks = 0; ks < 2; ks++) {
#pragma unroll
        for (int mi = 0; mi < 4; mi++) {
            int row = wm * 64 + mi * 16 + (mq & 1) * 8 + rowin;
            int col = ks * 16 + (mq >> 1) * 8;
            aoff[ks][mi] = (uint32_t)(row * 40 + col) * 2;
        }
#pragma unroll
        for (int np = 0; np < 2; np++) {
            int n = wn * 32 + np * 16 + (mq >> 1) * 8 + rowin;
            int col = ks * 16 + (mq & 1) * 8;
            boff[ks][np] = (uint32_t)(n * 40 + col) * 2;
        }
    }

    // 3-stage prologue
    load_chunk(0);
    if (nch > 1) load_chunk(1);
    asm volatile("cp.async.wait_group %0;" :: "n"(1) : "memory");  // chunk 0 ready
    __syncthreads();

    for (int i = 0; i < nch; i++) {
        if (i + 2 < nch) load_chunk(i + 2);
        const uint32_t tb = smbase + (i % NSTG) * BUFB;
        const uint32_t pAh = tb, pAl = tb + OPB, pBh = tb + 2 * OPB, pBl = tb + 3 * OPB;
#pragma unroll
        for (int ks = 0; ks < 2; ks++) {
            uint32_t ah[4][4], al[4][4], bh[4][2], bl[4][2], tmp[4];
#pragma unroll
            for (int mi = 0; mi < 4; mi++) {
                ldm_x4(ah[mi], pAh + aoff[ks][mi]);
                ldm_x4(al[mi], pAl + aoff[ks][mi]);
            }
#pragma unroll
            for (int np = 0; np < 2; np++) {
                ldm_x4(tmp, pBh + boff[ks][np]);
                bh[2*np][0] = tmp[0]; bh[2*np][1] = tmp[1];
                bh[2*np+1][0] = tmp[2]; bh[2*np+1][1] = tmp[3];
                ldm_x4(tmp, pBl + boff[ks][np]);
                bl[2*np][0] = tmp[0]; bl[2*np][1] = tmp[1];
                bl[2*np+1][0] = tmp[2]; bl[2*np+1][1] = tmp[3];
            }
            // term-major order: dependent MMAs on the same acc are 16 apart
#pragma unroll
            for (int mi = 0; mi < 4; mi++)
#pragma unroll
                for (int ni = 0; ni < 4; ni++)
                    mma16816(acc[mi][ni], ah[mi], bh[ni]);
#pragma unroll
            for (int mi = 0; mi < 4; mi++)
#pragma unroll
                for (int ni = 0; ni < 4; ni++)
                    mma16816(acc[mi][ni], ah[mi], bl[ni]);
#pragma unroll
            for (int mi = 0; mi < 4; mi++)
#pragma unroll
                for (int ni = 0; ni < 4; ni++)
                    mma16816(acc[mi][ni], al[mi], bh[ni]);
        }
        if (i + 1 < nch) {
            if (i + 2 < nch)
                asm volatile("cp.async.wait_group %0;" :: "n"(1) : "memory");
            else
                asm volatile("cp.async.wait_group %0;" :: "n"(0) : "memory");
            __syncthreads();
        }
    }

    // epilogue
#pragma unroll
    for (int mi = 0; mi < 4; mi++) {
#pragma unroll
        for (int ni = 0; ni < 4; ni++) {
            const int ch = m0 + wn * 32 + ni * 8 + lc;
            float b0 = 0.f, b1 = 0.f;
            if (MODE != 3) { b0 = __ldg(bias + ch); b1 = __ldg(bias + ch + 1); }
#pragma unroll
            for (int hh = 0; hh < 2; hh++) {
                const int pix = n0 + wm * 64 + mi * 16 + lr + hh * 8;
                const size_t prow = (size_t)b * HWSZ + pix;
                float v0 = acc[mi][ni][hh * 2] + b0;
                float v1 = acc[mi][ni][hh * 2 + 1] + b1;
                float2 vv; vv.x = v0; vv.y = v1;
                *(float2*)(outf + prow * (size_t)Mtot + ch) = vv;
                if (MODE == 0) {
                    size_t o = prow * 512 + ch;
                    bf16 h0, l0, h1, l1;
                    bsplit(v0, &h0, &l0);
                    bsplit(v1, &h1, &l1);
                    __nv_bfloat162 th, tl;
                    th.x = h0; th.y = h1; tl.x = l0; tl.y = l1;
                    *(__nv_bfloat162*)(oh + o) = th;
                    *(__nv_bfloat162*)(ol + o) = tl;
                }
            }
        }
    }
}

// ---------------- attention scores (reads q,k from fused qkv) -------------
__global__ __launch_bounds__(256)
void scores_kernel(const float* __restrict__ qkv, float* __restrict__ attn) {
    extern __shared__ float sm[];
    float* Qs = sm;
    float* Ks = sm + 96 * 64;
    const int fix = blockIdx.x, dir = blockIdx.y, b = blockIdx.z;
    const int tid = threadIdx.x;
    for (int idx = tid; idx < 96 * 32; idx += 256) {
        int p = idx >> 5, f = idx & 31;
        size_t row = (size_t)b * HWSZ + (dir == 0 ? p * IMG + fix : fix * IMG + p);
        float4 v = *(const float4*)&qkv[row * 640 + f * 4];
        if (f < 16) *(float4*)&Qs[p * 64 + f * 4] = v;
        else        *(float4*)&Ks[p * 68 + (f - 16) * 4] = v;
    }
    __syncthreads();
    for (int idx = tid; idx < 9216; idx += 256) {
        int p = idx / 96, r = idx - p * 96;
        const float* qp = &Qs[p * 64];
        const float* kp = &Ks[r * 68];
        float a0 = 0.f, a1 = 0.f, a2 = 0.f, a3 = 0.f;
#pragma unroll
        for (int t = 0; t < 16; t++) {
            float4 a = *(const float4*)&qp[t * 4];
            float4 k = *(const float4*)&kp[t * 4];
            a0 += a.x * k.x; a1 += a.y * k.y; a2 += a.z * k.z; a3 += a.w * k.w;
        }
        float val = (a0 + a1) + (a2 + a3);
        if (dir == 0 && r == p) val = -1e30f;
        size_t o = (dir == 0)
            ? ((size_t)b * HWSZ + p * IMG + fix) * 192 + r
            : ((size_t)b * HWSZ + fix * IMG + p) * 192 + 96 + r;
        attn[o] = val;
    }
}

__global__ __launch_bounds__(256)
void softmax_kernel(float* __restrict__ attn) {
    const int warp = threadIdx.x >> 5, lane = threadIdx.x & 31;
    const int pix = blockIdx.x * 8 + warp;
    float* p = attn + (size_t)pix * 192;
    float v[6];
#pragma unroll
    for (int t = 0; t < 6; t++) v[t] = p[lane + 32 * t];
    float m = v[0];
#pragma unroll
    for (int t = 1; t < 6; t++) m = fmaxf(m, v[t]);
#pragma unroll
    for (int off = 16; off > 0; off >>= 1) m = fmaxf(m, __shfl_xor_sync(0xffffffffu, m, off));
    float s = 0.f;
#pragma unroll
    for (int t = 0; t < 6; t++) { v[t] = __expf(v[t] - m); s += v[t]; }
#pragma unroll
    for (int off = 16; off > 0; off >>= 1) s += __shfl_xor_sync(0xffffffffu, s, off);
    float inv = 1.f / s;
#pragma unroll
    for (int t = 0; t < 6; t++) p[lane + 32 * t] = v[t] * inv;
}

// ---------------- aggregation along h (V = qkv + 128, stride 640) ---------
__global__ __launch_bounds__(256)
void agg_h_kernel(const float* __restrict__ V, const float* __restrict__ attn,
                  float* __restrict__ accb) {
    extern __shared__ float sm[];
    float* Vs = sm;
    float* At = sm + 96 * 128;
    const int w = blockIdx.x, c0 = blockIdx.y * 128, b = blockIdx.z;
    const int tid = threadIdx.x;
    for (int idx = tid; idx < 96 * 128; idx += 256) {
        int i = idx >> 7, cc = idx & 127;
        Vs[idx] = V[((size_t)b * HWSZ + i * IMG + w) * 640 + c0 + cc];
    }
    for (int idx = tid; idx < 9216; idx += 256) {
        int h = idx / 96, i = idx - h * 96;
        At[i * 100 + h] = attn[((size_t)b * HWSZ + h * IMG + w) * 192 + i];
    }
    __syncthreads();
    const int cc = tid & 127, h0 = (tid >> 7) * 48;
    float acc[48];
#pragma unroll
    for (int r = 0; r < 48; r++) acc[r] = 0.f;
    for (int i = 0; i < 96; i++) {
        float vv = Vs[i * 128 + cc];
        const float* ar = &At[i * 100 + h0];
#pragma unroll
        for (int r = 0; r < 12; r++) {
            float4 a = *(const float4*)&ar[r * 4];
            acc[4*r] += vv*a.x; acc[4*r+1] += vv*a.y; acc[4*r+2] += vv*a.z; acc[4*r+3] += vv*a.w;
        }
    }
#pragma unroll
    for (int h = 0; h < 48; h++)
        accb[((size_t)b * HWSZ + (h0 + h) * IMG + w) * 512 + c0 + cc] = acc[h];
}

// ---------------- aggregation along w + epilogue (emits bf16 hi/lo) ------
__global__ __launch_bounds__(256)
void agg_w_kernel(const float* __restrict__ V, const float* __restrict__ attn,
                  const float* __restrict__ accb, const float* __restrict__ zin,
                  const float* __restrict__ gamma, float* __restrict__ zout,
                  bf16* __restrict__ zh, bf16* __restrict__ zl) {
    extern __shared__ float sm[];
    float* Vs = sm;
    float* At = sm + 96 * 128;
    const int h = blockIdx.x, c0 = blockIdx.y * 128, b = blockIdx.z;
    const int tid = threadIdx.x;
    for (int idx = tid; idx < 96 * 128; idx += 256) {
        int j = idx >> 7, cc = idx & 127;
        Vs[idx] = V[((size_t)b * HWSZ + h * IMG + j) * 640 + c0 + cc];
    }
    for (int idx = tid; idx < 9216; idx += 256) {
        int w = idx / 96, j = idx - w * 96;
        At[j * 100 + w] = attn[((size_t)b * HWSZ + h * IMG + w) * 192 + 96 + j];
    }
    __syncthreads();
    const int cc = tid & 127, w0 = (tid >> 7) * 48;
    float acc[48];
#pragma unroll
    for (int r = 0; r < 48; r++) acc[r] = 0.f;
    for (int j = 0; j < 96; j++) {
        float vv = Vs[j * 128 + cc];
        const float* ar = &At[j * 100 + w0];
#pragma unroll
        for (int r = 0; r < 12; r++) {
            float4 a = *(const float4*)&ar[r * 4];
            acc[4*r] += vv*a.x; acc[4*r+1] += vv*a.y; acc[4*r+2] += vv*a.z; acc[4*r+3] += vv*a.w;
        }
    }
    const float g = gamma[0];
#pragma unroll
    for (int w = 0; w < 48; w++) {
        size_t o = ((size_t)b * HWSZ + h * IMG + w0 + w) * 512 + c0 + cc;
        float val = g * (acc[w] + accb[o]) + zin[o];
        zout[o] = val;
        bsplit(val, &zh[o], &zl[o]);
    }
}

// ---------------- GroupNorm ----------------
__global__ __launch_bounds__(256)
void gn_stats_cl(const float* __restrict__ x, float* __restrict__ stat) {
    const int b = blockIdx.x >> 5, gg = blockIdx.x & 31;
    const float* base = x + (size_t)b * HWSZ * 512 + gg * 16;
    float s = 0.f, ss = 0.f;
    for (int idx = threadIdx.x; idx < HWSZ * 4; idx += 256) {
        int pix = idx >> 2, q = idx & 3;
        float4 v = *(const float4*)(base + (size_t)pix * 512 + q * 4);
        s  += (v.x + v.y) + (v.z + v.w);
        ss += (v.x*v.x + v.y*v.y) + (v.z*v.z + v.w*v.w);
    }
    __shared__ float rs[8], rss[8];
    const int lane = threadIdx.x & 31, warp = threadIdx.x >> 5;
#pragma unroll
    for (int off = 16; off > 0; off >>= 1) {
        s  += __shfl_xor_sync(0xffffffffu, s, off);
        ss += __shfl_xor_sync(0xffffffffu, ss, off);
    }
    if (lane == 0) { rs[warp] = s; rss[warp] = ss; }
    __syncthreads();
    if (threadIdx.x == 0) {
        float S = 0.f, SS = 0.f;
#pragma unroll
        for (int i = 0; i < 8; i++) { S += rs[i]; SS += rss[i]; }
        float mean = S / 147456.f;
        float var = SS / 147456.f - mean * mean;
        stat[2 * blockIdx.x] = mean;
        stat[2 * blockIdx.x + 1] = rsqrtf(var + 1e-5f);
    }
}

__global__ __launch_bounds__(256)
void gn_out_kernel(const float* __restrict__ cl, const float* __restrict__ gam,
                   const float* __restrict__ bet, const float* __restrict__ stat,
                   float* __restrict__ out) {
    __shared__ float t[32][33];
    const int p0 = blockIdx.x * 32, c0 = blockIdx.y * 32, b = blockIdx.z;
    const int tx = threadIdx.x & 31, ty = threadIdx.x >> 5;
#pragma unroll
    for (int k = 0; k < 4; k++) {
        int pl = ty + k * 8;
        t[pl][tx] = cl[((size_t)b * HWSZ + p0 + pl) * 512 + c0 + tx];
    }
    __syncthreads();
#pragma unroll
    for (int k = 0; k < 4; k++) {
        int c = c0 + ty + k * 8;
        int sg = b * 32 + (c >> 4);
        float sc = stat[2 * sg + 1] * gam[c];
        float sh = bet[c] - stat[2 * sg] * sc;
        out[((size_t)b * 512 + c) * HWSZ + p0 + tx] = t[tx][ty + k * 8] * sc + sh;
    }
}

// ---------------- launch ----------------
extern "C" void kernel_launch(void* const* d_in, const int* in_sizes, int n_in,
                              void* d_out, int out_size) {
    const float* x   = (const float*)d_in[0];
    const float* c1w = (const float*)d_in[1];
    const float* c1b = (const float*)d_in[2];
    const float* qw  = (const float*)d_in[3];
    const float* qb  = (const float*)d_in[4];
    const float* kw  = (const float*)d_in[5];
    const float* kb  = (const float*)d_in[6];
    const float* vw  = (const float*)d_in[7];
    const float* vb  = (const float*)d_in[8];
    const float* gam = (const float*)d_in[9];
    const float* cow = (const float*)d_in[10];
    const float* gng = (const float*)d_in[11];
    const float* gnb = (const float*)d_in[12];
    float* out = (float*)d_out;

    void *p;
#define SYM(var, sym) cudaGetSymbolAddress(&p, sym); auto* var = (decltype(&sym[0]))p;
    SYM(xh, g_xh) SYM(xl, g_xl) SYM(zh, g_zh) SYM(zl, g_zl)
    SYM(z, g_z) SYM(z2, g_z2) SYM(qkv, g_qkv)
    SYM(attn, g_attn) SYM(acc, g_acc) SYM(cl, g_cl)
    SYM(c1h, g_c1h) SYM(c1l, g_c1l) SYM(qvh, g_qvh) SYM(qvl, g_qvl)
    SYM(w9h, g_w9h) SYM(w9l, g_w9l)
    SYM(bqv, g_bqv) SYM(st, g_stat)
#undef SYM

    const int SC_SM = 50688, AG_SM = 87552;
    cudaFuncSetAttribute(scores_kernel, cudaFuncAttributeMaxDynamicSharedMemorySize, SC_SM);
    cudaFuncSetAttribute(agg_h_kernel,  cudaFuncAttributeMaxDynamicSharedMemorySize, AG_SM);
    cudaFuncSetAttribute(agg_w_kernel,  cudaFuncAttributeMaxDynamicSharedMemorySize, AG_SM);
    cudaFuncSetAttribute(mma_gemm<0>, cudaFuncAttributeMaxDynamicSharedMemorySize, MG_SMEM);
    cudaFuncSetAttribute(mma_gemm<2>, cudaFuncAttributeMaxDynamicSharedMemorySize, MG_SMEM);
    cudaFuncSetAttribute(mma_gemm<3>, cudaFuncAttributeMaxDynamicSharedMemorySize, MG_SMEM);

    split_x<<<dim3(288, 64, 2), 256>>>(x, xh, xl);
    split_weights<<<(C1SZ + QVSZ + W9SZ + 255) / 256, 256>>>(
        c1w, qw, kw, vw, qb, kb, vb, cow, c1h, c1l, qvh, qvl, w9h, w9l, bqv);

    mma_gemm<0><<<dim3(72, 4, 2), 256, MG_SMEM>>>(xh, xl, c1h, c1l, c1b, z, zh, zl, 2048, 512);

    for (int it = 0; it < 2; it++) {
        float* zi = it ? z2 : z;
        float* zo = it ? z : z2;
        mma_gemm<2><<<dim3(72, 5, 2), 256, MG_SMEM>>>(zh, zl, qvh, qvl, bqv, qkv, nullptr, nullptr, 512, 640);
        scores_kernel<<<dim3(96, 2, 2), 256, SC_SM>>>(qkv, attn);
        softmax_kernel<<<2304, 256>>>(attn);
        agg_h_kernel<<<dim3(96, 4, 2), 256, AG_SM>>>(qkv + 128, attn, acc);
        agg_w_kernel<<<dim3(96, 4, 2), 256, AG_SM>>>(qkv + 128, attn, acc, zi, gam, zo, zh, zl);
    }

    mma_gemm<3><<<dim3(72, 4, 2), 256, MG_SMEM>>>(zh, zl, w9h, w9l, nullptr, cl, nullptr, nullptr, 512, 512);
    gn_stats_cl<<<64, 256>>>(cl, st);
    gn_out_kernel<<<dim3(288, 16, 2), 256>>>(cl, gng, gnb, st, out);
}

// round 12
// speedup vs baseline: 1.0057x; 1.0057x over previous
#include <cuda_runtime.h>
#include <cuda_bf16.h>
#include <cstdint>

#define HWSZ 9216
#define IMG  96
typedef __nv_bfloat16 bf16;

// ---------------- device scratch ----------------
__device__ bf16 g_xh[2 * HWSZ * 2048];
__device__ bf16 g_xl[2 * HWSZ * 2048];
__device__ bf16 g_zh[2 * HWSZ * 512];
__device__ bf16 g_zl[2 * HWSZ * 512];
__device__ float g_z   [2 * HWSZ * 512];
__device__ float g_z2  [2 * HWSZ * 512];
__device__ float g_qkv [2 * HWSZ * 640];   // [q 0:64 | k 64:128 | v 128:640]
__device__ float g_attn[2 * HWSZ * 192];
__device__ float g_acc [2 * HWSZ * 512];
__device__ float g_cl  [2 * HWSZ * 512];
__device__ bf16 g_c1h[512 * 2048], g_c1l[512 * 2048];
__device__ bf16 g_qvh[640 * 512],  g_qvl[640 * 512];
__device__ bf16 g_w9h[9 * 512 * 512], g_w9l[9 * 512 * 512];
__device__ float g_bqv[640];
__device__ float g_stat[128];

// ---------------- helpers ----------------
__device__ __forceinline__ uint32_t s2u(const void* p) {
    uint32_t a;
    asm("{ .reg .u64 t; cvta.to.shared.u64 t, %1; cvt.u32.u64 %0, t; }" : "=r"(a) : "l"(p));
    return a;
}
__device__ __forceinline__ void bsplit(float v, bf16* h, bf16* l) {
    bf16 hh = __float2bfloat16(v);
    *h = hh;
    *l = __float2bfloat16(v - __bfloat162float(hh));
}
__device__ __forceinline__ void mma16816(float* d, const uint32_t* a, const uint32_t* b) {
    asm volatile(
        "mma.sync.aligned.m16n8k16.row.col.f32.bf16.bf16.f32 "
        "{%0,%1,%2,%3}, {%4,%5,%6,%7}, {%8,%9}, {%0,%1,%2,%3};"
        : "+f"(d[0]), "+f"(d[1]), "+f"(d[2]), "+f"(d[3])
        : "r"(a[0]), "r"(a[1]), "r"(a[2]), "r"(a[3]), "r"(b[0]), "r"(b[1]));
}
__device__ __forceinline__ void cpasync16(uint32_t s, const void* g) {
    asm volatile("cp.async.cg.shared.global [%0], [%1], 16;" :: "r"(s), "l"(g));
}
__device__ __forceinline__ void ldm_x4(uint32_t* r, uint32_t addr) {
    asm volatile("ldmatrix.sync.aligned.m8n8.x4.shared.b16 {%0,%1,%2,%3}, [%4];"
                 : "=r"(r[0]), "=r"(r[1]), "=r"(r[2]), "=r"(r[3]) : "r"(addr));
}

// ---------------- packing / splitting ----------------
__global__ void split_x(const float* __restrict__ x, bf16* __restrict__ xh,
                        bf16* __restrict__ xl) {
    __shared__ float t[32][33];
    const int p0 = blockIdx.x * 32, c0 = blockIdx.y * 32, b = blockIdx.z;
    const int tx = threadIdx.x & 31, ty = threadIdx.x >> 5;
#pragma unroll
    for (int k = 0; k < 4; k++) {
        int cc = ty + k * 8;
        t[cc][tx] = x[((size_t)b * 2048 + c0 + cc) * HWSZ + p0 + tx];
    }
    __syncthreads();
#pragma unroll
    for (int k = 0; k < 4; k++) {
        int pl = ty + k * 8;
        float v = t[tx][pl];
        size_t o = ((size_t)b * HWSZ + p0 + pl) * 2048 + c0 + tx;
        bsplit(v, &xh[o], &xl[o]);
    }
}

#define C1SZ  (512 * 2048)
#define QVSZ  (640 * 512)
#define W9SZ  (9 * 512 * 512)
__global__ void split_weights(const float* __restrict__ c1w,
                              const float* __restrict__ qw, const float* __restrict__ kw,
                              const float* __restrict__ vw, const float* __restrict__ qb,
                              const float* __restrict__ kb, const float* __restrict__ vb,
                              const float* __restrict__ cow,
                              bf16* __restrict__ c1h, bf16* __restrict__ c1l,
                              bf16* __restrict__ qvh, bf16* __restrict__ qvl,
                              bf16* __restrict__ w9h, bf16* __restrict__ w9l,
                              float* __restrict__ bqv) {
    int i = blockIdx.x * 256 + threadIdx.x;
    if (i < 640)
        bqv[i] = (i < 64) ? qb[i] : (i < 128) ? kb[i - 64] : vb[i - 128];
    if (i < C1SZ) {
        bsplit(c1w[i], &c1h[i], &c1l[i]);
    } else if (i < C1SZ + QVSZ) {
        int j = i - C1SZ;
        int m = j >> 9, k = j & 511;
        float v = (m < 64) ? qw[m * 512 + k]
                : (m < 128) ? kw[(m - 64) * 512 + k]
                            : vw[(m - 128) * 512 + k];
        bsplit(v, &qvh[j], &qvl[j]);
    } else if (i < C1SZ + QVSZ + W9SZ) {
        int d = i - C1SZ - QVSZ;
        int s = d / (512 * 512), r = d % (512 * 512);
        int o = r >> 9, ic = r & 511;
        bsplit(cow[(o * 512 + ic) * 9 + s], &w9h[d], &w9l[d]);
    }
}

// ---------------- bf16-split tensor-core GEMM, 512 threads / 16 warps -----
// D[128 pix][128 ch] = A[pix][K].B[ch][K]^T via Ah*Bh + Ah*Bl + Al*Bh
// Each warp owns a 32x32 sub-tile (2 m-frags x 4 n-frags).
#define OPSZ 5120            // elems per operand tile (128*40)
#define OPB  10240           // bytes per operand tile
#define BUFE 20480           // elems per stage buffer (4 operands)
#define BUFB 40960           // bytes per stage buffer
#define NSTG 3
#define MG_SMEM (4864 + NSTG * BUFB)
template <int MODE>
__global__ __launch_bounds__(512, 1)
void mma_gemm(const bf16* __restrict__ Ah, const bf16* __restrict__ Al,
              const bf16* __restrict__ Bh, const bf16* __restrict__ Bl,
              const float* __restrict__ bias, float* __restrict__ outf,
              bf16* __restrict__ oh, bf16* __restrict__ ol,
              int K, int Mtot)
{
    extern __shared__ char smem[];
    int* srcn = (int*)smem;
    bf16* tiles = (bf16*)(smem + 4864);
    const uint32_t smbase = s2u(tiles);
    const int tid = threadIdx.x, wid = tid >> 5, lane = tid & 31;
    const int n0 = blockIdx.x * 128, m0 = blockIdx.y * 128, b = blockIdx.z;

    if (MODE == 3 && tid < 128) {
        int n = n0 + tid, y = n / IMG, x = n - y * IMG;
#pragma unroll
        for (int s = 0; s < 9; s++) {
            int sy = y + s / 3 - 1, sx = x + s % 3 - 1;
            srcn[s * 128 + tid] = (sy >= 0 && sy < IMG && sx >= 0 && sx < IMG) ? sy * IMG + sx : -1;
        }
    }
    __syncthreads();

    // loaders: 4 groups of 128 threads, one operand each
    const int g = tid >> 7, u = tid & 127, q = u & 3, rs = u >> 2;
    const bf16* srcp = (g == 0) ? Ah : (g == 1) ? Al : (g == 2) ? Bh : Bl;
    const int nch = (MODE == 3) ? 144 : (K >> 5);

    auto load_chunk = [&](int i) {
        bf16* t = tiles + (i % NSTG) * BUFE + g * OPSZ;
        int s = 0, k0;
        if (MODE == 3) { s = i >> 4; k0 = (i & 15) << 5; } else { k0 = i << 5; }
#pragma unroll
        for (int j = 0; j < 4; j++) {
            int row = rs + j * 32;
            uint32_t sa = s2u(t + row * 40 + q * 8);
            if (g < 2) {
                long rn = -1;
                if (MODE == 3) { int sn = srcn[s * 128 + row]; if (sn >= 0) rn = sn; }
                else rn = n0 + row;
                if (rn >= 0)
                    cpasync16(sa, srcp + ((size_t)b * HWSZ + rn) * (size_t)K + k0 + q * 8);
                else
                    *(uint4*)(t + row * 40 + q * 8) = make_uint4(0, 0, 0, 0);
            } else {
                size_t mrow = (MODE == 3) ? ((size_t)s * 512 + m0 + row) : (size_t)(m0 + row);
                cpasync16(sa, srcp + mrow * (size_t)K + k0 + q * 8);
            }
        }
        asm volatile("cp.async.commit_group;" ::: "memory");
    };

    float acc[2][4][4];
#pragma unroll
    for (int mi = 0; mi < 2; mi++)
#pragma unroll
        for (int ni = 0; ni < 4; ni++)
#pragma unroll
            for (int r = 0; r < 4; r++) acc[mi][ni][r] = 0.f;

    const int wm = wid >> 2, wn = wid & 3;   // 4x4 warp grid, 32x32 each
    const int lr = lane >> 2, lc = (lane & 3) * 2;
    const int mq = lane >> 3, rowin = lane & 7;

    uint32_t aoff[2][2], boff[2][2];
#pragma unroll
    for (int ks = 0; ks < 2; ks++) {
#pragma unroll
        for (int mi = 0; mi < 2; mi++) {
            int row = wm * 32 + mi * 16 + (mq & 1) * 8 + rowin;
            int col = ks * 16 + (mq >> 1) * 8;
            aoff[ks][mi] = (uint32_t)(row * 40 + col) * 2;
        }
#pragma unroll
        for (int np = 0; np < 2; np++) {
            int n = wn * 32 + np * 16 + (mq >> 1) * 8 + rowin;
            int col = ks * 16 + (mq & 1) * 8;
            boff[ks][np] = (uint32_t)(n * 40 + col) * 2;
        }
    }

    load_chunk(0);
    if (nch > 1) load_chunk(1);
    asm volatile("cp.async.wait_group %0;" :: "n"(1) : "memory");
    __syncthreads();

    for (int i = 0; i < nch; i++) {
        if (i + 2 < nch) load_chunk(i + 2);
        const uint32_t tb = smbase + (i % NSTG) * BUFB;
        const uint32_t pAh = tb, pAl = tb + OPB, pBh = tb + 2 * OPB, pBl = tb + 3 * OPB;
#pragma unroll
        for (int ks = 0; ks < 2; ks++) {
            uint32_t ah[2][4], al[2][4], bh[4][2], bl[4][2], tmp[4];
#pragma unroll
            for (int mi = 0; mi < 2; mi++) {
                ldm_x4(ah[mi], pAh + aoff[ks][mi]);
                ldm_x4(al[mi], pAl + aoff[ks][mi]);
            }
#pragma unroll
            for (int np = 0; np < 2; np++) {
                ldm_x4(tmp, pBh + boff[ks][np]);
                bh[2*np][0] = tmp[0]; bh[2*np][1] = tmp[1];
                bh[2*np+1][0] = tmp[2]; bh[2*np+1][1] = tmp[3];
                ldm_x4(tmp, pBl + boff[ks][np]);
                bl[2*np][0] = tmp[0]; bl[2*np][1] = tmp[1];
                bl[2*np+1][0] = tmp[2]; bl[2*np+1][1] = tmp[3];
            }
            // term-major: dependent MMAs on same acc are 8 apart
#pragma unroll
            for (int mi = 0; mi < 2; mi++)
#pragma unroll
                for (int ni = 0; ni < 4; ni++)
                    mma16816(acc[mi][ni], ah[mi], bh[ni]);
#pragma unroll
            for (int mi = 0; mi < 2; mi++)
#pragma unroll
                for (int ni = 0; ni < 4; ni++)
                    mma16816(acc[mi][ni], ah[mi], bl[ni]);
#pragma unroll
            for (int mi = 0; mi < 2; mi++)
#pragma unroll
                for (int ni = 0; ni < 4; ni++)
                    mma16816(acc[mi][ni], al[mi], bh[ni]);
        }
        if (i + 1 < nch) {
            if (i + 2 < nch)
                asm volatile("cp.async.wait_group %0;" :: "n"(1) : "memory");
            else
                asm volatile("cp.async.wait_group %0;" :: "n"(0) : "memory");
            __syncthreads();
        }
    }

    // epilogue
#pragma unroll
    for (int mi = 0; mi < 2; mi++) {
#pragma unroll
        for (int ni = 0; ni < 4; ni++) {
            const int ch = m0 + wn * 32 + ni * 8 + lc;
            float b0 = 0.f, b1 = 0.f;
            if (MODE != 3) { b0 = __ldg(bias + ch); b1 = __ldg(bias + ch + 1); }
#pragma unroll
            for (int hh = 0; hh < 2; hh++) {
                const int pix = n0 + wm * 32 + mi * 16 + lr + hh * 8;
                const size_t prow = (size_t)b * HWSZ + pix;
                float v0 = acc[mi][ni][hh * 2] + b0;
                float v1 = acc[mi][ni][hh * 2 + 1] + b1;
                float2 vv; vv.x = v0; vv.y = v1;
                *(float2*)(outf + prow * (size_t)Mtot + ch) = vv;
                if (MODE == 0) {
                    size_t o = prow * 512 + ch;
                    bf16 h0, l0, h1, l1;
                    bsplit(v0, &h0, &l0);
                    bsplit(v1, &h1, &l1);
                    __nv_bfloat162 th, tl;
                    th.x = h0; th.y = h1; tl.x = l0; tl.y = l1;
                    *(__nv_bfloat162*)(oh + o) = th;
                    *(__nv_bfloat162*)(ol + o) = tl;
                }
            }
        }
    }
}

// ---------------- attention scores (reads q,k from fused qkv) -------------
__global__ __launch_bounds__(256)
void scores_kernel(const float* __restrict__ qkv, float* __restrict__ attn) {
    extern __shared__ float sm[];
    float* Qs = sm;
    float* Ks = sm + 96 * 64;
    const int fix = blockIdx.x, dir = blockIdx.y, b = blockIdx.z;
    const int tid = threadIdx.x;
    for (int idx = tid; idx < 96 * 32; idx += 256) {
        int p = idx >> 5, f = idx & 31;
        size_t row = (size_t)b * HWSZ + (dir == 0 ? p * IMG + fix : fix * IMG + p);
        float4 v = *(const float4*)&qkv[row * 640 + f * 4];
        if (f < 16) *(float4*)&Qs[p * 64 + f * 4] = v;
        else        *(float4*)&Ks[p * 68 + (f - 16) * 4] = v;
    }
    __syncthreads();
    for (int idx = tid; idx < 9216; idx += 256) {
        int p = idx / 96, r = idx - p * 96;
        const float* qp = &Qs[p * 64];
        const float* kp = &Ks[r * 68];
        float a0 = 0.f, a1 = 0.f, a2 = 0.f, a3 = 0.f;
#pragma unroll
        for (int t = 0; t < 16; t++) {
            float4 a = *(const float4*)&qp[t * 4];
            float4 k = *(const float4*)&kp[t * 4];
            a0 += a.x * k.x; a1 += a.y * k.y; a2 += a.z * k.z; a3 += a.w * k.w;
        }
        float val = (a0 + a1) + (a2 + a3);
        if (dir == 0 && r == p) val = -1e30f;
        size_t o = (dir == 0)
            ? ((size_t)b * HWSZ + p * IMG + fix) * 192 + r
            : ((size_t)b * HWSZ + fix * IMG + p) * 192 + 96 + r;
        attn[o] = val;
    }
}

__global__ __launch_bounds__(256)
void softmax_kernel(float* __restrict__ attn) {
    const int warp = threadIdx.x >> 5, lane = threadIdx.x & 31;
    const int pix = blockIdx.x * 8 + warp;
    float* p = attn + (size_t)pix * 192;
    float v[6];
#pragma unroll
    for (int t = 0; t < 6; t++) v[t] = p[lane + 32 * t];
    float m = v[0];
#pragma unroll
    for (int t = 1; t < 6; t++) m = fmaxf(m, v[t]);
#pragma unroll
    for (int off = 16; off > 0; off >>= 1) m = fmaxf(m, __shfl_xor_sync(0xffffffffu, m, off));
    float s = 0.f;
#pragma unroll
    for (int t = 0; t < 6; t++) { v[t] = __expf(v[t] - m); s += v[t]; }
#pragma unroll
    for (int off = 16; off > 0; off >>= 1) s += __shfl_xor_sync(0xffffffffu, s, off);
    float inv = 1.f / s;
#pragma unroll
    for (int t = 0; t < 6; t++) p[lane + 32 * t] = v[t] * inv;
}

// ---------------- aggregation along h (V = qkv + 128, stride 640) ---------
__global__ __launch_bounds__(256)
void agg_h_kernel(const float* __restrict__ V, const float* __restrict__ attn,
                  float* __restrict__ accb) {
    extern __shared__ float sm[];
    float* Vs = sm;
    float* At = sm + 96 * 128;
    const int w = blockIdx.x, c0 = blockIdx.y * 128, b = blockIdx.z;
    const int tid = threadIdx.x;
    for (int idx = tid; idx < 96 * 128; idx += 256) {
        int i = idx >> 7, cc = idx & 127;
        Vs[idx] = V[((size_t)b * HWSZ + i * IMG + w) * 640 + c0 + cc];
    }
    for (int idx = tid; idx < 9216; idx += 256) {
        int h = idx / 96, i = idx - h * 96;
        At[i * 100 + h] = attn[((size_t)b * HWSZ + h * IMG + w) * 192 + i];
    }
    __syncthreads();
    const int cc = tid & 127, h0 = (tid >> 7) * 48;
    float acc[48];
#pragma unroll
    for (int r = 0; r < 48; r++) acc[r] = 0.f;
    for (int i = 0; i < 96; i++) {
        float vv = Vs[i * 128 + cc];
        const float* ar = &At[i * 100 + h0];
#pragma unroll
        for (int r = 0; r < 12; r++) {
            float4 a = *(const float4*)&ar[r * 4];
            acc[4*r] += vv*a.x; acc[4*r+1] += vv*a.y; acc[4*r+2] += vv*a.z; acc[4*r+3] += vv*a.w;
        }
    }
#pragma unroll
    for (int h = 0; h < 48; h++)
        accb[((size_t)b * HWSZ + (h0 + h) * IMG + w) * 512 + c0 + cc] = acc[h];
}

// ---------------- aggregation along w + epilogue (emits bf16 hi/lo) ------
__global__ __launch_bounds__(256)
void agg_w_kernel(const float* __restrict__ V, const float* __restrict__ attn,
                  const float* __restrict__ accb, const float* __restrict__ zin,
                  const float* __restrict__ gamma, float* __restrict__ zout,
                  bf16* __restrict__ zh, bf16* __restrict__ zl) {
    extern __shared__ float sm[];
    float* Vs = sm;
    float* At = sm + 96 * 128;
    const int h = blockIdx.x, c0 = blockIdx.y * 128, b = blockIdx.z;
    const int tid = threadIdx.x;
    for (int idx = tid; idx < 96 * 128; idx += 256) {
        int j = idx >> 7, cc = idx & 127;
        Vs[idx] = V[((size_t)b * HWSZ + h * IMG + j) * 640 + c0 + cc];
    }
    for (int idx = tid; idx < 9216; idx += 256) {
        int w = idx / 96, j = idx - w * 96;
        At[j * 100 + w] = attn[((size_t)b * HWSZ + h * IMG + w) * 192 + 96 + j];
    }
    __syncthreads();
    const int cc = tid & 127, w0 = (tid >> 7) * 48;
    float acc[48];
#pragma unroll
    for (int r = 0; r < 48; r++) acc[r] = 0.f;
    for (int j = 0; j < 96; j++) {
        float vv = Vs[j * 128 + cc];
        const float* ar = &At[j * 100 + w0];
#pragma unroll
        for (int r = 0; r < 12; r++) {
            float4 a = *(const float4*)&ar[r * 4];
            acc[4*r] += vv*a.x; acc[4*r+1] += vv*a.y; acc[4*r+2] += vv*a.z; acc[4*r+3] += vv*a.w;
        }
    }
    const float g = gamma[0];
#pragma unroll
    for (int w = 0; w < 48; w++) {
        size_t o = ((size_t)b * HWSZ + h * IMG + w0 + w) * 512 + c0 + cc;
        float val = g * (acc[w] + accb[o]) + zin[o];
        zout[o] = val;
        bsplit(val, &zh[o], &zl[o]);
    }
}

// ---------------- GroupNorm ----------------
__global__ __launch_bounds__(256)
void gn_stats_cl(const float* __restrict__ x, float* __restrict__ stat) {
    const int b = blockIdx.x >> 5, gg = blockIdx.x & 31;
    const float* base = x + (size_t)b * HWSZ * 512 + gg * 16;
    float s = 0.f, ss = 0.f;
    for (int idx = threadIdx.x; idx < HWSZ * 4; idx += 256) {
        int pix = idx >> 2, q = idx & 3;
        float4 v = *(const float4*)(base + (size_t)pix * 512 + q * 4);
        s  += (v.x + v.y) + (v.z + v.w);
        ss += (v.x*v.x + v.y*v.y) + (v.z*v.z + v.w*v.w);
    }
    __shared__ float rs[8], rss[8];
    const int lane = threadIdx.x & 31, warp = threadIdx.x >> 5;
#pragma unroll
    for (int off = 16; off > 0; off >>= 1) {
        s  += __shfl_xor_sync(0xffffffffu, s, off);
        ss += __shfl_xor_sync(0xffffffffu, ss, off);
    }
    if (lane == 0) { rs[warp] = s; rss[warp] = ss; }
    __syncthreads();
    if (threadIdx.x == 0) {
        float S = 0.f, SS = 0.f;
#pragma unroll
        for (int i = 0; i < 8; i++) { S += rs[i]; SS += rss[i]; }
        float mean = S / 147456.f;
        float var = SS / 147456.f - mean * mean;
        stat[2 * blockIdx.x] = mean;
        stat[2 * blockIdx.x + 1] = rsqrtf(var + 1e-5f);
    }
}

__global__ __launch_bounds__(256)
void gn_out_kernel(const float* __restrict__ cl, const float* __restrict__ gam,
                   const float* __restrict__ bet, const float* __restrict__ stat,
                   float* __restrict__ out) {
    __shared__ float t[32][33];
    const int p0 = blockIdx.x * 32, c0 = blockIdx.y * 32, b = blockIdx.z;
    const int tx = threadIdx.x & 31, ty = threadIdx.x >> 5;
#pragma unroll
    for (int k = 0; k < 4; k++) {
        int pl = ty + k * 8;
        t[pl][tx] = cl[((size_t)b * HWSZ + p0 + pl) * 512 + c0 + tx];
    }
    __syncthreads();
#pragma unroll
    for (int k = 0; k < 4; k++) {
        int c = c0 + ty + k * 8;
        int sg = b * 32 + (c >> 4);
        float sc = stat[2 * sg + 1] * gam[c];
        float sh = bet[c] - stat[2 * sg] * sc;
        out[((size_t)b * 512 + c) * HWSZ + p0 + tx] = t[tx][ty + k * 8] * sc + sh;
    }
}

// ---------------- launch ----------------
extern "C" void kernel_launch(void* const* d_in, const int* in_sizes, int n_in,
                              void* d_out, int out_size) {
    const float* x   = (const float*)d_in[0];
    const float* c1w = (const float*)d_in[1];
    const float* c1b = (const float*)d_in[2];
    const float* qw  = (const float*)d_in[3];
    const float* qb  = (const float*)d_in[4];
    const float* kw  = (const float*)d_in[5];
    const float* kb  = (const float*)d_in[6];
    const float* vw  = (const float*)d_in[7];
    const float* vb  = (const float*)d_in[8];
    const float* gam = (const float*)d_in[9];
    const float* cow = (const float*)d_in[10];
    const float* gng = (const float*)d_in[11];
    const float* gnb = (const float*)d_in[12];
    float* out = (float*)d_out;

    void *p;
#define SYM(var, sym) cudaGetSymbolAddress(&p, sym); auto* var = (decltype(&sym[0]))p;
    SYM(xh, g_xh) SYM(xl, g_xl) SYM(zh, g_zh) SYM(zl, g_zl)
    SYM(z, g_z) SYM(z2, g_z2) SYM(qkv, g_qkv)
    SYM(attn, g_attn) SYM(acc, g_acc) SYM(cl, g_cl)
    SYM(c1h, g_c1h) SYM(c1l, g_c1l) SYM(qvh, g_qvh) SYM(qvl, g_qvl)
    SYM(w9h, g_w9h) SYM(w9l, g_w9l)
    SYM(bqv, g_bqv) SYM(st, g_stat)
#undef SYM

    const int SC_SM = 50688, AG_SM = 87552;
    cudaFuncSetAttribute(scores_kernel, cudaFuncAttributeMaxDynamicSharedMemorySize, SC_SM);
    cudaFuncSetAttribute(agg_h_kernel,  cudaFuncAttributeMaxDynamicSharedMemorySize, AG_SM);
    cudaFuncSetAttribute(agg_w_kernel,  cudaFuncAttributeMaxDynamicSharedMemorySize, AG_SM);
    cudaFuncSetAttribute(mma_gemm<0>, cudaFuncAttributeMaxDynamicSharedMemorySize, MG_SMEM);
    cudaFuncSetAttribute(mma_gemm<2>, cudaFuncAttributeMaxDynamicSharedMemorySize, MG_SMEM);
    cudaFuncSetAttribute(mma_gemm<3>, cudaFuncAttributeMaxDynamicSharedMemorySize, MG_SMEM);

    split_x<<<dim3(288, 64, 2), 256>>>(x, xh, xl);
    split_weights<<<(C1SZ + QVSZ + W9SZ + 255) / 256, 256>>>(
        c1w, qw, kw, vw, qb, kb, vb, cow, c1h, c1l, qvh, qvl, w9h, w9l, bqv);

    mma_gemm<0><<<dim3(72, 4, 2), 512, MG_SMEM>>>(xh, xl, c1h, c1l, c1b, z, zh, zl, 2048, 512);

    for (int it = 0; it < 2; it++) {
        float* zi = it ? z2 : z;
        float* zo = it ? z : z2;
        mma_gemm<2><<<dim3(72, 5, 2), 512, MG_SMEM>>>(zh, zl, qvh, qvl, bqv, qkv, nullptr, nullptr, 512, 640);
        scores_kernel<<<dim3(96, 2, 2), 256, SC_SM>>>(qkv, attn);
        softmax_kernel<<<2304, 256>>>(attn);
        agg_h_kernel<<<dim3(96, 4, 2), 256, AG_SM>>>(qkv + 128, attn, acc);
        agg_w_kernel<<<dim3(96, 4, 2), 256, AG_SM>>>(qkv + 128, attn, acc, zi, gam, zo, zh, zl);
    }

    mma_gemm<3><<<dim3(72, 4, 2), 512, MG_SMEM>>>(zh, zl, w9h, w9l, nullptr, cl, nullptr, nullptr, 512, 512);
    gn_stats_cl<<<64, 256>>>(cl, st);
    gn_out_kernel<<<dim3(288, 16, 2), 256>>>(cl, gng, gnb, st, out);
}

// round 13
// speedup vs baseline: 1.2315x; 1.2245x over previous
#include <cuda_runtime.h>
#include <cuda_fp16.h>
#include <cstdint>

#define HWSZ 9216
#define IMG  96
typedef __half f16;

// ---------------- device scratch ----------------
__device__ f16 g_xh[2 * HWSZ * 2048];
__device__ f16 g_xl[2 * HWSZ * 2048];
__device__ f16 g_zh[2 * HWSZ * 512];
__device__ f16 g_zl[2 * HWSZ * 512];
__device__ float g_z   [2 * HWSZ * 512];
__device__ float g_z2  [2 * HWSZ * 512];
__device__ float g_qkv [2 * HWSZ * 640];   // [q 0:64 | k 64:128 | v 128:640]
__device__ float g_attn[2 * HWSZ * 192];
__device__ float g_acc [2 * HWSZ * 512];
__device__ float g_cl  [2 * HWSZ * 512];
__device__ f16 g_c1h[512 * 2048];                 // conv1 weights (x64, single for 2-term... hi)
__device__ f16 g_c1l[512 * 2048];                 // unused in 2-term but kept for layout
__device__ f16 g_qvh[640 * 512],  g_qvl[640 * 512];
__device__ f16 g_w9h[9 * 512 * 512], g_w9l[9 * 512 * 512];
__device__ float g_bqv[640];
__device__ float g_stat[128];

#define WSCALE 64.0f
#define INVWS  0.015625f

// ---------------- helpers ----------------
__device__ __forceinline__ uint32_t s2u(const void* p) {
    uint32_t a;
    asm("{ .reg .u64 t; cvta.to.shared.u64 t, %1; cvt.u32.u64 %0, t; }" : "=r"(a) : "l"(p));
    return a;
}
__device__ __forceinline__ void hsplit(float v, f16* h, f16* l) {
    f16 hh = __float2half(v);
    *h = hh;
    *l = __float2half(v - __half2float(hh));
}
__device__ __forceinline__ void mma16816(float* d, const uint32_t* a, const uint32_t* b) {
    asm volatile(
        "mma.sync.aligned.m16n8k16.row.col.f32.f16.f16.f32 "
        "{%0,%1,%2,%3}, {%4,%5,%6,%7}, {%8,%9}, {%0,%1,%2,%3};"
        : "+f"(d[0]), "+f"(d[1]), "+f"(d[2]), "+f"(d[3])
        : "r"(a[0]), "r"(a[1]), "r"(a[2]), "r"(a[3]), "r"(b[0]), "r"(b[1]));
}
__device__ __forceinline__ void cpasync16(uint32_t s, const void* g) {
    asm volatile("cp.async.cg.shared.global [%0], [%1], 16;" :: "r"(s), "l"(g));
}
__device__ __forceinline__ void ldm_x4(uint32_t* r, uint32_t addr) {
    asm volatile("ldmatrix.sync.aligned.m8n8.x4.shared.b16 {%0,%1,%2,%3}, [%4];"
                 : "=r"(r[0]), "=r"(r[1]), "=r"(r[2]), "=r"(r[3]) : "r"(addr));
}

// ---------------- packing / splitting ----------------
__global__ void split_x(const float* __restrict__ x, f16* __restrict__ xh,
                        f16* __restrict__ xl) {
    __shared__ float t[32][33];
    const int p0 = blockIdx.x * 32, c0 = blockIdx.y * 32, b = blockIdx.z;
    const int tx = threadIdx.x & 31, ty = threadIdx.x >> 5;
#pragma unroll
    for (int k = 0; k < 4; k++) {
        int cc = ty + k * 8;
        t[cc][tx] = x[((size_t)b * 2048 + c0 + cc) * HWSZ + p0 + tx];
    }
    __syncthreads();
#pragma unroll
    for (int k = 0; k < 4; k++) {
        int pl = ty + k * 8;
        float v = t[tx][pl];
        size_t o = ((size_t)b * HWSZ + p0 + pl) * 2048 + c0 + tx;
        hsplit(v, &xh[o], &xl[o]);
    }
}

#define C1SZ  (512 * 2048)
#define QVSZ  (640 * 512)
#define W9SZ  (9 * 512 * 512)
__global__ void split_weights(const float* __restrict__ c1w,
                              const float* __restrict__ qw, const float* __restrict__ kw,
                              const float* __restrict__ vw, const float* __restrict__ qb,
                              const float* __restrict__ kb, const float* __restrict__ vb,
                              const float* __restrict__ cow,
                              f16* __restrict__ c1h, f16* __restrict__ c1l,
                              f16* __restrict__ qvh, f16* __restrict__ qvl,
                              f16* __restrict__ w9h, f16* __restrict__ w9l,
                              float* __restrict__ bqv) {
    int i = blockIdx.x * 256 + threadIdx.x;
    if (i < 640)
        bqv[i] = (i < 64) ? qb[i] : (i < 128) ? kb[i - 64] : vb[i - 128];
    if (i < C1SZ) {
        hsplit(WSCALE * c1w[i], &c1h[i], &c1l[i]);
    } else if (i < C1SZ + QVSZ) {
        int j = i - C1SZ;
        int m = j >> 9, k = j & 511;
        float v = (m < 64) ? qw[m * 512 + k]
                : (m < 128) ? kw[(m - 64) * 512 + k]
                            : vw[(m - 128) * 512 + k];
        hsplit(WSCALE * v, &qvh[j], &qvl[j]);
    } else if (i < C1SZ + QVSZ + W9SZ) {
        int d = i - C1SZ - QVSZ;
        int s = d / (512 * 512), r = d % (512 * 512);
        int o = r >> 9, ic = r & 511;
        hsplit(WSCALE * cow[(o * 512 + ic) * 9 + s], &w9h[d], &w9l[d]);
    }
}

// ---------------- fp16-split tensor-core GEMM, 512 threads / 16 warps -----
// D[128 pix][128 ch] = (1/64) * (A[pix][K] . (64 B[ch][K])^T) + bias
// TERMS=3: Ah*Bh + Ah*Bl + Al*Bh ; TERMS=2: Ah*Bh + Al*Bh (B not split)
// MODE 0: conv1 (2-term, fp32 + f16 hi/lo out), 2: qkv (3-term), 3: conv3 (2-term, 9 shifts)
#define OPSZ 5120
#define OPB  10240
#define BUFE 20480
#define BUFB 40960
#define NSTG 3
#define MG_SMEM (4864 + NSTG * BUFB)
template <int MODE>
__global__ __launch_bounds__(512, 1)
void mma_gemm(const f16* __restrict__ Ah, const f16* __restrict__ Al,
              const f16* __restrict__ Bh, const f16* __restrict__ Bl,
              const float* __restrict__ bias, float* __restrict__ outf,
              f16* __restrict__ oh, f16* __restrict__ ol,
              int K, int Mtot)
{
    constexpr int TERMS = (MODE == 2) ? 3 : 2;
    extern __shared__ char smem[];
    int* srcn = (int*)smem;
    f16* tiles = (f16*)(smem + 4864);
    const uint32_t smbase = s2u(tiles);
    const int tid = threadIdx.x, wid = tid >> 5, lane = tid & 31;
    const int n0 = blockIdx.x * 128, m0 = blockIdx.y * 128, b = blockIdx.z;

    if (MODE == 3 && tid < 128) {
        int n = n0 + tid, y = n / IMG, x = n - y * IMG;
#pragma unroll
        for (int s = 0; s < 9; s++) {
            int sy = y + s / 3 - 1, sx = x + s % 3 - 1;
            srcn[s * 128 + tid] = (sy >= 0 && sy < IMG && sx >= 0 && sx < IMG) ? sy * IMG + sx : -1;
        }
    }
    __syncthreads();

    // loaders: 4 groups of 128 threads; group 3 (Bl) idle when TERMS==2
    const int g = tid >> 7, u = tid & 127, q = u & 3, rs = u >> 2;
    const f16* srcp = (g == 0) ? Ah : (g == 1) ? Al : (g == 2) ? Bh : Bl;
    const int nch = (MODE == 3) ? 144 : (K >> 5);

    auto load_chunk = [&](int i) {
        if (TERMS == 3 || g < 3) {
            f16* t = tiles + (i % NSTG) * BUFE + g * OPSZ;
            int s = 0, k0;
            if (MODE == 3) { s = i >> 4; k0 = (i & 15) << 5; } else { k0 = i << 5; }
#pragma unroll
            for (int j = 0; j < 4; j++) {
                int row = rs + j * 32;
                uint32_t sa = s2u(t + row * 40 + q * 8);
                if (g < 2) {
                    long rn = -1;
                    if (MODE == 3) { int sn = srcn[s * 128 + row]; if (sn >= 0) rn = sn; }
                    else rn = n0 + row;
                    if (rn >= 0)
                        cpasync16(sa, srcp + ((size_t)b * HWSZ + rn) * (size_t)K + k0 + q * 8);
                    else
                        *(uint4*)(t + row * 40 + q * 8) = make_uint4(0, 0, 0, 0);
                } else {
                    size_t mrow = (MODE == 3) ? ((size_t)s * 512 + m0 + row) : (size_t)(m0 + row);
                    cpasync16(sa, srcp + mrow * (size_t)K + k0 + q * 8);
                }
            }
        }
        asm volatile("cp.async.commit_group;" ::: "memory");
    };

    float acc[2][4][4];
#pragma unroll
    for (int mi = 0; mi < 2; mi++)
#pragma unroll
        for (int ni = 0; ni < 4; ni++)
#pragma unroll
            for (int r = 0; r < 4; r++) acc[mi][ni][r] = 0.f;

    const int wm = wid >> 2, wn = wid & 3;
    const int lr = lane >> 2, lc = (lane & 3) * 2;
    const int mq = lane >> 3, rowin = lane & 7;

    uint32_t aoff[2][2], boff[2][2];
#pragma unroll
    for (int ks = 0; ks < 2; ks++) {
#pragma unroll
        for (int mi = 0; mi < 2; mi++) {
            int row = wm * 32 + mi * 16 + (mq & 1) * 8 + rowin;
            int col = ks * 16 + (mq >> 1) * 8;
            aoff[ks][mi] = (uint32_t)(row * 40 + col) * 2;
        }
#pragma unroll
        for (int np = 0; np < 2; np++) {
            int n = wn * 32 + np * 16 + (mq >> 1) * 8 + rowin;
            int col = ks * 16 + (mq & 1) * 8;
            boff[ks][np] = (uint32_t)(n * 40 + col) * 2;
        }
    }

    load_chunk(0);
    if (nch > 1) load_chunk(1);
    asm volatile("cp.async.wait_group %0;" :: "n"(1) : "memory");
    __syncthreads();

    for (int i = 0; i < nch; i++) {
        if (i + 2 < nch) load_chunk(i + 2);
        const uint32_t tb = smbase + (i % NSTG) * BUFB;
        const uint32_t pAh = tb, pAl = tb + OPB, pBh = tb + 2 * OPB, pBl = tb + 3 * OPB;
#pragma unroll
        for (int ks = 0; ks < 2; ks++) {
            uint32_t ah[2][4], al[2][4], bh[4][2], bl[4][2], tmp[4];
#pragma unroll
            for (int mi = 0; mi < 2; mi++) {
                ldm_x4(ah[mi], pAh + aoff[ks][mi]);
                ldm_x4(al[mi], pAl + aoff[ks][mi]);
            }
#pragma unroll
            for (int np = 0; np < 2; np++) {
                ldm_x4(tmp, pBh + boff[ks][np]);
                bh[2*np][0] = tmp[0]; bh[2*np][1] = tmp[1];
                bh[2*np+1][0] = tmp[2]; bh[2*np+1][1] = tmp[3];
                if (TERMS == 3) {
                    ldm_x4(tmp, pBl + boff[ks][np]);
                    bl[2*np][0] = tmp[0]; bl[2*np][1] = tmp[1];
                    bl[2*np+1][0] = tmp[2]; bl[2*np+1][1] = tmp[3];
                }
            }
#pragma unroll
            for (int mi = 0; mi < 2; mi++)
#pragma unroll
                for (int ni = 0; ni < 4; ni++)
                    mma16816(acc[mi][ni], ah[mi], bh[ni]);
#pragma unroll
            for (int mi = 0; mi < 2; mi++)
#pragma unroll
                for (int ni = 0; ni < 4; ni++)
                    mma16816(acc[mi][ni], al[mi], bh[ni]);
            if (TERMS == 3) {
#pragma unroll
                for (int mi = 0; mi < 2; mi++)
#pragma unroll
                    for (int ni = 0; ni < 4; ni++)
                        mma16816(acc[mi][ni], ah[mi], bl[ni]);
            }
        }
        if (i + 1 < nch) {
            if (i + 2 < nch)
                asm volatile("cp.async.wait_group %0;" :: "n"(1) : "memory");
            else
                asm volatile("cp.async.wait_group %0;" :: "n"(0) : "memory");
            __syncthreads();
        }
    }

    // epilogue: unscale weights (x64) then bias
#pragma unroll
    for (int mi = 0; mi < 2; mi++) {
#pragma unroll
        for (int ni = 0; ni < 4; ni++) {
            const int ch = m0 + wn * 32 + ni * 8 + lc;
            float b0 = 0.f, b1 = 0.f;
            if (MODE != 3) { b0 = __ldg(bias + ch); b1 = __ldg(bias + ch + 1); }
#pragma unroll
            for (int hh = 0; hh < 2; hh++) {
                const int pix = n0 + wm * 32 + mi * 16 + lr + hh * 8;
                const size_t prow = (size_t)b * HWSZ + pix;
                float v0 = acc[mi][ni][hh * 2] * INVWS + b0;
                float v1 = acc[mi][ni][hh * 2 + 1] * INVWS + b1;
                float2 vv; vv.x = v0; vv.y = v1;
                *(float2*)(outf + prow * (size_t)Mtot + ch) = vv;
                if (MODE == 0) {
                    size_t o = prow * 512 + ch;
                    f16 h0, l0, h1, l1;
                    hsplit(v0, &h0, &l0);
                    hsplit(v1, &h1, &l1);
                    *(__half2*)(oh + o) = __halves2half2(h0, h1);
                    *(__half2*)(ol + o) = __halves2half2(l0, l1);
                }
            }
        }
    }
}

// ---------------- attention scores (reads q,k from fused qkv) -------------
__global__ __launch_bounds__(256)
void scores_kernel(const float* __restrict__ qkv, float* __restrict__ attn) {
    extern __shared__ float sm[];
    float* Qs = sm;
    float* Ks = sm + 96 * 64;
    const int fix = blockIdx.x, dir = blockIdx.y, b = blockIdx.z;
    const int tid = threadIdx.x;
    for (int idx = tid; idx < 96 * 32; idx += 256) {
        int p = idx >> 5, f = idx & 31;
        size_t row = (size_t)b * HWSZ + (dir == 0 ? p * IMG + fix : fix * IMG + p);
        float4 v = *(const float4*)&qkv[row * 640 + f * 4];
        if (f < 16) *(float4*)&Qs[p * 64 + f * 4] = v;
        else        *(float4*)&Ks[p * 68 + (f - 16) * 4] = v;
    }
    __syncthreads();
    for (int idx = tid; idx < 9216; idx += 256) {
        int p = idx / 96, r = idx - p * 96;
        const float* qp = &Qs[p * 64];
        const float* kp = &Ks[r * 68];
        float a0 = 0.f, a1 = 0.f, a2 = 0.f, a3 = 0.f;
#pragma unroll
        for (int t = 0; t < 16; t++) {
            float4 a = *(const float4*)&qp[t * 4];
            float4 k = *(const float4*)&kp[t * 4];
            a0 += a.x * k.x; a1 += a.y * k.y; a2 += a.z * k.z; a3 += a.w * k.w;
        }
        float val = (a0 + a1) + (a2 + a3);
        if (dir == 0 && r == p) val = -1e30f;
        size_t o = (dir == 0)
            ? ((size_t)b * HWSZ + p * IMG + fix) * 192 + r
            : ((size_t)b * HWSZ + fix * IMG + p) * 192 + 96 + r;
        attn[o] = val;
    }
}

__global__ __launch_bounds__(256)
void softmax_kernel(float* __restrict__ attn) {
    const int warp = threadIdx.x >> 5, lane = threadIdx.x & 31;
    const int pix = blockIdx.x * 8 + warp;
    float* p = attn + (size_t)pix * 192;
    float v[6];
#pragma unroll
    for (int t = 0; t < 6; t++) v[t] = p[lane + 32 * t];
    float m = v[0];
#pragma unroll
    for (int t = 1; t < 6; t++) m = fmaxf(m, v[t]);
#pragma unroll
    for (int off = 16; off > 0; off >>= 1) m = fmaxf(m, __shfl_xor_sync(0xffffffffu, m, off));
    float s = 0.f;
#pragma unroll
    for (int t = 0; t < 6; t++) { v[t] = __expf(v[t] - m); s += v[t]; }
#pragma unroll
    for (int off = 16; off > 0; off >>= 1) s += __shfl_xor_sync(0xffffffffu, s, off);
    float inv = 1.f / s;
#pragma unroll
    for (int t = 0; t < 6; t++) p[lane + 32 * t] = v[t] * inv;
}

// ---------------- aggregation along h (V = qkv + 128, stride 640) ---------
__global__ __launch_bounds__(256)
void agg_h_kernel(const float* __restrict__ V, const float* __restrict__ attn,
                  float* __restrict__ accb) {
    extern __shared__ float sm[];
    float* Vs = sm;
    float* At = sm + 96 * 128;
    const int w = blockIdx.x, c0 = blockIdx.y * 128, b = blockIdx.z;
    const int tid = threadIdx.x;
    for (int idx = tid; idx < 96 * 128; idx += 256) {
        int i = idx >> 7, cc = idx & 127;
        Vs[idx] = V[((size_t)b * HWSZ + i * IMG + w) * 640 + c0 + cc];
    }
    for (int idx = tid; idx < 9216; idx += 256) {
        int h = idx / 96, i = idx - h * 96;
        At[i * 100 + h] = attn[((size_t)b * HWSZ + h * IMG + w) * 192 + i];
    }
    __syncthreads();
    const int cc = tid & 127, h0 = (tid >> 7) * 48;
    float acc[48];
#pragma unroll
    for (int r = 0; r < 48; r++) acc[r] = 0.f;
    for (int i = 0; i < 96; i++) {
        float vv = Vs[i * 128 + cc];
        const float* ar = &At[i * 100 + h0];
#pragma unroll
        for (int r = 0; r < 12; r++) {
            float4 a = *(const float4*)&ar[r * 4];
            acc[4*r] += vv*a.x; acc[4*r+1] += vv*a.y; acc[4*r+2] += vv*a.z; acc[4*r+3] += vv*a.w;
        }
    }
#pragma unroll
    for (int h = 0; h < 48; h++)
        accb[((size_t)b * HWSZ + (h0 + h) * IMG + w) * 512 + c0 + cc] = acc[h];
}

// ---------------- aggregation along w + epilogue (emits f16 hi/lo) -------
__global__ __launch_bounds__(256)
void agg_w_kernel(const float* __restrict__ V, const float* __restrict__ attn,
                  const float* __restrict__ accb, const float* __restrict__ zin,
                  const float* __restrict__ gamma, float* __restrict__ zout,
                  f16* __restrict__ zh, f16* __restrict__ zl) {
    extern __shared__ float sm[];
    float* Vs = sm;
    float* At = sm + 96 * 128;
    const int h = blockIdx.x, c0 = blockIdx.y * 128, b = blockIdx.z;
    const int tid = threadIdx.x;
    for (int idx = tid; idx < 96 * 128; idx += 256) {
        int j = idx >> 7, cc = idx & 127;
        Vs[idx] = V[((size_t)b * HWSZ + h * IMG + j) * 640 + c0 + cc];
    }
    for (int idx = tid; idx < 9216; idx += 256) {
        int w = idx / 96, j = idx - w * 96;
        At[j * 100 + w] = attn[((size_t)b * HWSZ + h * IMG + w) * 192 + 96 + j];
    }
    __syncthreads();
    const int cc = tid & 127, w0 = (tid >> 7) * 48;
    float acc[48];
#pragma unroll
    for (int r = 0; r < 48; r++) acc[r] = 0.f;
    for (int j = 0; j < 96; j++) {
        float vv = Vs[j * 128 + cc];
        const float* ar = &At[j * 100 + w0];
#pragma unroll
        for (int r = 0; r < 12; r++) {
            float4 a = *(const float4*)&ar[r * 4];
            acc[4*r] += vv*a.x; acc[4*r+1] += vv*a.y; acc[4*r+2] += vv*a.z; acc[4*r+3] += vv*a.w;
        }
    }
    const float g = gamma[0];
#pragma unroll
    for (int w = 0; w < 48; w++) {
        size_t o = ((size_t)b * HWSZ + h * IMG + w0 + w) * 512 + c0 + cc;
        float val = g * (acc[w] + accb[o]) + zin[o];
        zout[o] = val;
        hsplit(val, &zh[o], &zl[o]);
    }
}

// ---------------- GroupNorm ----------------
__global__ __launch_bounds__(256)
void gn_stats_cl(const float* __restrict__ x, float* __restrict__ stat) {
    const int b = blockIdx.x >> 5, gg = blockIdx.x & 31;
    const float* base = x + (size_t)b * HWSZ * 512 + gg * 16;
    float s = 0.f, ss = 0.f;
    for (int idx = threadIdx.x; idx < HWSZ * 4; idx += 256) {
        int pix = idx >> 2, q = idx & 3;
        float4 v = *(const float4*)(base + (size_t)pix * 512 + q * 4);
        s  += (v.x + v.y) + (v.z + v.w);
        ss += (v.x*v.x + v.y*v.y) + (v.z*v.z + v.w*v.w);
    }
    __shared__ float rs[8], rss[8];
    const int lane = threadIdx.x & 31, warp = threadIdx.x >> 5;
#pragma unroll
    for (int off = 16; off > 0; off >>= 1) {
        s  += __shfl_xor_sync(0xffffffffu, s, off);
        ss += __shfl_xor_sync(0xffffffffu, ss, off);
    }
    if (lane == 0) { rs[warp] = s; rss[warp] = ss; }
    __syncthreads();
    if (threadIdx.x == 0) {
        float S = 0.f, SS = 0.f;
#pragma unroll
        for (int i = 0; i < 8; i++) { S += rs[i]; SS += rss[i]; }
        float mean = S / 147456.f;
        float var = SS / 147456.f - mean * mean;
        stat[2 * blockIdx.x] = mean;
        stat[2 * blockIdx.x + 1] = rsqrtf(var + 1e-5f);
    }
}

__global__ __launch_bounds__(256)
void gn_out_kernel(const float* __restrict__ cl, const float* __restrict__ gam,
                   const float* __restrict__ bet, const float* __restrict__ stat,
                   float* __restrict__ out) {
    __shared__ float t[32][33];
    const int p0 = blockIdx.x * 32, c0 = blockIdx.y * 32, b = blockIdx.z;
    const int tx = threadIdx.x & 31, ty = threadIdx.x >> 5;
#pragma unroll
    for (int k = 0; k < 4; k++) {
        int pl = ty + k * 8;
        t[pl][tx] = cl[((size_t)b * HWSZ + p0 + pl) * 512 + c0 + tx];
    }
    __syncthreads();
#pragma unroll
    for (int k = 0; k < 4; k++) {
        int c = c0 + ty + k * 8;
        int sg = b * 32 + (c >> 4);
        float sc = stat[2 * sg + 1] * gam[c];
        float sh = bet[c] - stat[2 * sg] * sc;
        out[((size_t)b * 512 + c) * HWSZ + p0 + tx] = t[tx][ty + k * 8] * sc + sh;
    }
}

// ---------------- launch ----------------
extern "C" void kernel_launch(void* const* d_in, const int* in_sizes, int n_in,
                              void* d_out, int out_size) {
    const float* x   = (const float*)d_in[0];
    const float* c1w = (const float*)d_in[1];
    const float* c1b = (const float*)d_in[2];
    const float* qw  = (const float*)d_in[3];
    const float* qb  = (const float*)d_in[4];
    const float* kw  = (const float*)d_in[5];
    const float* kb  = (const float*)d_in[6];
    const float* vw  = (const float*)d_in[7];
    const float* vb  = (const float*)d_in[8];
    const float* gam = (const float*)d_in[9];
    const float* cow = (const float*)d_in[10];
    const float* gng = (const float*)d_in[11];
    const float* gnb = (const float*)d_in[12];
    float* out = (float*)d_out;

    void *p;
#define SYM(var, sym) cudaGetSymbolAddress(&p, sym); auto* var = (decltype(&sym[0]))p;
    SYM(xh, g_xh) SYM(xl, g_xl) SYM(zh, g_zh) SYM(zl, g_zl)
    SYM(z, g_z) SYM(z2, g_z2) SYM(qkv, g_qkv)
    SYM(attn, g_attn) SYM(acc, g_acc) SYM(cl, g_cl)
    SYM(c1h, g_c1h) SYM(c1l, g_c1l) SYM(qvh, g_qvh) SYM(qvl, g_qvl)
    SYM(w9h, g_w9h) SYM(w9l, g_w9l)
    SYM(bqv, g_bqv) SYM(st, g_stat)
#undef SYM

    const int SC_SM = 50688, AG_SM = 87552;
    cudaFuncSetAttribute(scores_kernel, cudaFuncAttributeMaxDynamicSharedMemorySize, SC_SM);
    cudaFuncSetAttribute(agg_h_kernel,  cudaFuncAttributeMaxDynamicSharedMemorySize, AG_SM);
    cudaFuncSetAttribute(agg_w_kernel,  cudaFuncAttributeMaxDynamicSharedMemorySize, AG_SM);
    cudaFuncSetAttribute(mma_gemm<0>, cudaFuncAttributeMaxDynamicSharedMemorySize, MG_SMEM);
    cudaFuncSetAttribute(mma_gemm<2>, cudaFuncAttributeMaxDynamicSharedMemorySize, MG_SMEM);
    cudaFuncSetAttribute(mma_gemm<3>, cudaFuncAttributeMaxDynamicSharedMemorySize, MG_SMEM);

    split_x<<<dim3(288, 64, 2), 256>>>(x, xh, xl);
    split_weights<<<(C1SZ + QVSZ + W9SZ + 255) / 256, 256>>>(
        c1w, qw, kw, vw, qb, kb, vb, cow, c1h, c1l, qvh, qvl, w9h, w9l, bqv);

    mma_gemm<0><<<dim3(72, 4, 2), 512, MG_SMEM>>>(xh, xl, c1h, c1l, c1b, z, zh, zl, 2048, 512);

    for (int it = 0; it < 2; it++) {
        float* zi = it ? z2 : z;
        float* zo = it ? z : z2;
        mma_gemm<2><<<dim3(72, 5, 2), 512, MG_SMEM>>>(zh, zl, qvh, qvl, bqv, qkv, nullptr, nullptr, 512, 640);
        scores_kernel<<<dim3(96, 2, 2), 256, SC_SM>>>(qkv, attn);
        softmax_kernel<<<2304, 256>>>(attn);
        agg_h_kernel<<<dim3(96, 4, 2), 256, AG_SM>>>(qkv + 128, attn, acc);
        agg_w_kernel<<<dim3(96, 4, 2), 256, AG_SM>>>(qkv + 128, attn, acc, zi, gam, zo, zh, zl);
    }

    mma_gemm<3><<<dim3(72, 4, 2), 512, MG_SMEM>>>(zh, zl, w9h, w9l, nullptr, cl, nullptr, nullptr, 512, 512);
    gn_stats_cl<<<64, 256>>>(cl, st);
    gn_out_kernel<<<dim3(288, 16, 2), 256>>>(cl, gng, gnb, st, out);
}

// round 14
// speedup vs baseline: 1.3513x; 1.0973x over previous
#include <cuda_runtime.h>
#include <cuda_fp16.h>
#include <cstdint>

#define HWSZ 9216
#define IMG  96
typedef __half f16;

// ---------------- device scratch ----------------
__device__ f16 g_xh[2 * HWSZ * 2048];
__device__ f16 g_xl[2 * HWSZ * 2048];
__device__ f16 g_zh[2 * HWSZ * 512];
__device__ f16 g_zl[2 * HWSZ * 512];
__device__ float g_z   [2 * HWSZ * 512];
__device__ float g_z2  [2 * HWSZ * 512];
__device__ float g_qkv [2 * HWSZ * 640];   // [q 0:64 | k 64:128 | v 128:640]
__device__ float g_attn[2 * HWSZ * 192];
__device__ float g_acc [2 * HWSZ * 512];
__device__ float g_cl  [2 * HWSZ * 512];
__device__ f16 g_c1h[512 * 2048];
__device__ f16 g_c1l[512 * 2048];
__device__ f16 g_qvh[640 * 512],  g_qvl[640 * 512];
__device__ f16 g_w9h[9 * 512 * 512], g_w9l[9 * 512 * 512];
__device__ float g_bqv[640];
__device__ float g_stat[128];

#define WSCALE 64.0f
#define INVWS  0.015625f

// ---------------- helpers ----------------
__device__ __forceinline__ uint32_t s2u(const void* p) {
    uint32_t a;
    asm("{ .reg .u64 t; cvta.to.shared.u64 t, %1; cvt.u32.u64 %0, t; }" : "=r"(a) : "l"(p));
    return a;
}
__device__ __forceinline__ void hsplit(float v, f16* h, f16* l) {
    f16 hh = __float2half(v);
    *h = hh;
    *l = __float2half(v - __half2float(hh));
}
__device__ __forceinline__ void mma16816(float* d, const uint32_t* a, const uint32_t* b) {
    asm volatile(
        "mma.sync.aligned.m16n8k16.row.col.f32.f16.f16.f32 "
        "{%0,%1,%2,%3}, {%4,%5,%6,%7}, {%8,%9}, {%0,%1,%2,%3};"
        : "+f"(d[0]), "+f"(d[1]), "+f"(d[2]), "+f"(d[3])
        : "r"(a[0]), "r"(a[1]), "r"(a[2]), "r"(a[3]), "r"(b[0]), "r"(b[1]));
}
__device__ __forceinline__ void cpasync16(uint32_t s, const void* g) {
    asm volatile("cp.async.cg.shared.global [%0], [%1], 16;" :: "r"(s), "l"(g));
}
__device__ __forceinline__ void ldm_x4(uint32_t* r, uint32_t addr) {
    asm volatile("ldmatrix.sync.aligned.m8n8.x4.shared.b16 {%0,%1,%2,%3}, [%4];"
                 : "=r"(r[0]), "=r"(r[1]), "=r"(r[2]), "=r"(r[3]) : "r"(addr));
}

// ---------------- packing / splitting ----------------
__global__ void split_x(const float* __restrict__ x, f16* __restrict__ xh,
                        f16* __restrict__ xl) {
    __shared__ float t[32][33];
    const int p0 = blockIdx.x * 32, c0 = blockIdx.y * 32, b = blockIdx.z;
    const int tx = threadIdx.x & 31, ty = threadIdx.x >> 5;
#pragma unroll
    for (int k = 0; k < 4; k++) {
        int cc = ty + k * 8;
        t[cc][tx] = x[((size_t)b * 2048 + c0 + cc) * HWSZ + p0 + tx];
    }
    __syncthreads();
#pragma unroll
    for (int k = 0; k < 4; k++) {
        int pl = ty + k * 8;
        float v = t[tx][pl];
        size_t o = ((size_t)b * HWSZ + p0 + pl) * 2048 + c0 + tx;
        hsplit(v, &xh[o], &xl[o]);
    }
}

#define C1SZ  (512 * 2048)
#define QVSZ  (640 * 512)
#define W9SZ  (9 * 512 * 512)
__global__ void split_weights(const float* __restrict__ c1w,
                              const float* __restrict__ qw, const float* __restrict__ kw,
                              const float* __restrict__ vw, const float* __restrict__ qb,
                              const float* __restrict__ kb, const float* __restrict__ vb,
                              const float* __restrict__ cow,
                              f16* __restrict__ c1h, f16* __restrict__ c1l,
                              f16* __restrict__ qvh, f16* __restrict__ qvl,
                              f16* __restrict__ w9h, f16* __restrict__ w9l,
                              float* __restrict__ bqv) {
    int i = blockIdx.x * 256 + threadIdx.x;
    if (i < 640)
        bqv[i] = (i < 64) ? qb[i] : (i < 128) ? kb[i - 64] : vb[i - 128];
    if (i < C1SZ) {
        hsplit(WSCALE * c1w[i], &c1h[i], &c1l[i]);
    } else if (i < C1SZ + QVSZ) {
        int j = i - C1SZ;
        int m = j >> 9, k = j & 511;
        float v = (m < 64) ? qw[m * 512 + k]
                : (m < 128) ? kw[(m - 64) * 512 + k]
                            : vw[(m - 128) * 512 + k];
        hsplit(WSCALE * v, &qvh[j], &qvl[j]);
    } else if (i < C1SZ + QVSZ + W9SZ) {
        int d = i - C1SZ - QVSZ;
        int s = d / (512 * 512), r = d % (512 * 512);
        int o = r >> 9, ic = r & 511;
        hsplit(WSCALE * cow[(o * 512 + ic) * 9 + s], &w9h[d], &w9l[d]);
    }
}

// ---------------- fp16-split tensor-core GEMM, 512 threads / 16 warps -----
#define OPSZ 5120
#define OPB  10240
#define BUFE 20480
#define BUFB 40960
#define NSTG 3
#define MG_SMEM (4864 + NSTG * BUFB)
template <int MODE>
__global__ __launch_bounds__(512, 1)
void mma_gemm(const f16* __restrict__ Ah, const f16* __restrict__ Al,
              const f16* __restrict__ Bh, const f16* __restrict__ Bl,
              const float* __restrict__ bias, float* __restrict__ outf,
              f16* __restrict__ oh, f16* __restrict__ ol,
              int K, int Mtot)
{
    constexpr int TERMS = (MODE == 2) ? 3 : 2;
    extern __shared__ char smem[];
    int* srcn = (int*)smem;
    f16* tiles = (f16*)(smem + 4864);
    const uint32_t smbase = s2u(tiles);
    const int tid = threadIdx.x, wid = tid >> 5, lane = tid & 31;
    const int n0 = blockIdx.x * 128, m0 = blockIdx.y * 128, b = blockIdx.z;

    if (MODE == 3 && tid < 128) {
        int n = n0 + tid, y = n / IMG, x = n - y * IMG;
#pragma unroll
        for (int s = 0; s < 9; s++) {
            int sy = y + s / 3 - 1, sx = x + s % 3 - 1;
            srcn[s * 128 + tid] = (sy >= 0 && sy < IMG && sx >= 0 && sx < IMG) ? sy * IMG + sx : -1;
        }
    }
    __syncthreads();

    const int g = tid >> 7, u = tid & 127, q = u & 3, rs = u >> 2;
    const f16* srcp = (g == 0) ? Ah : (g == 1) ? Al : (g == 2) ? Bh : Bl;
    const int nch = (MODE == 3) ? 144 : (K >> 5);

    auto load_chunk = [&](int i) {
        if (TERMS == 3 || g < 3) {
            f16* t = tiles + (i % NSTG) * BUFE + g * OPSZ;
            int s = 0, k0;
            if (MODE == 3) { s = i >> 4; k0 = (i & 15) << 5; } else { k0 = i << 5; }
#pragma unroll
            for (int j = 0; j < 4; j++) {
                int row = rs + j * 32;
                uint32_t sa = s2u(t + row * 40 + q * 8);
                if (g < 2) {
                    long rn = -1;
                    if (MODE == 3) { int sn = srcn[s * 128 + row]; if (sn >= 0) rn = sn; }
                    else rn = n0 + row;
                    if (rn >= 0)
                        cpasync16(sa, srcp + ((size_t)b * HWSZ + rn) * (size_t)K + k0 + q * 8);
                    else
                        *(uint4*)(t + row * 40 + q * 8) = make_uint4(0, 0, 0, 0);
                } else {
                    size_t mrow = (MODE == 3) ? ((size_t)s * 512 + m0 + row) : (size_t)(m0 + row);
                    cpasync16(sa, srcp + mrow * (size_t)K + k0 + q * 8);
                }
            }
        }
        asm volatile("cp.async.commit_group;" ::: "memory");
    };

    float acc[2][4][4];
#pragma unroll
    for (int mi = 0; mi < 2; mi++)
#pragma unroll
        for (int ni = 0; ni < 4; ni++)
#pragma unroll
            for (int r = 0; r < 4; r++) acc[mi][ni][r] = 0.f;

    const int wm = wid >> 2, wn = wid & 3;
    const int lr = lane >> 2, lc = (lane & 3) * 2;
    const int mq = lane >> 3, rowin = lane & 7;

    uint32_t aoff[2][2], boff[2][2];
#pragma unroll
    for (int ks = 0; ks < 2; ks++) {
#pragma unroll
        for (int mi = 0; mi < 2; mi++) {
            int row = wm * 32 + mi * 16 + (mq & 1) * 8 + rowin;
            int col = ks * 16 + (mq >> 1) * 8;
            aoff[ks][mi] = (uint32_t)(row * 40 + col) * 2;
        }
#pragma unroll
        for (int np = 0; np < 2; np++) {
            int n = wn * 32 + np * 16 + (mq >> 1) * 8 + rowin;
            int col = ks * 16 + (mq & 1) * 8;
            boff[ks][np] = (uint32_t)(n * 40 + col) * 2;
        }
    }

    load_chunk(0);
    if (nch > 1) load_chunk(1);
    asm volatile("cp.async.wait_group %0;" :: "n"(1) : "memory");
    __syncthreads();

    for (int i = 0; i < nch; i++) {
        if (i + 2 < nch) load_chunk(i + 2);
        const uint32_t tb = smbase + (i % NSTG) * BUFB;
        const uint32_t pAh = tb, pAl = tb + OPB, pBh = tb + 2 * OPB, pBl = tb + 3 * OPB;
#pragma unroll
        for (int ks = 0; ks < 2; ks++) {
            uint32_t ah[2][4], al[2][4], bh[4][2], bl[4][2], tmp[4];
#pragma unroll
            for (int mi = 0; mi < 2; mi++) {
                ldm_x4(ah[mi], pAh + aoff[ks][mi]);
                ldm_x4(al[mi], pAl + aoff[ks][mi]);
            }
#pragma unroll
            for (int np = 0; np < 2; np++) {
                ldm_x4(tmp, pBh + boff[ks][np]);
                bh[2*np][0] = tmp[0]; bh[2*np][1] = tmp[1];
                bh[2*np+1][0] = tmp[2]; bh[2*np+1][1] = tmp[3];
                if (TERMS == 3) {
                    ldm_x4(tmp, pBl + boff[ks][np]);
                    bl[2*np][0] = tmp[0]; bl[2*np][1] = tmp[1];
                    bl[2*np+1][0] = tmp[2]; bl[2*np+1][1] = tmp[3];
                }
            }
#pragma unroll
            for (int mi = 0; mi < 2; mi++)
#pragma unroll
                for (int ni = 0; ni < 4; ni++)
                    mma16816(acc[mi][ni], ah[mi], bh[ni]);
#pragma unroll
            for (int mi = 0; mi < 2; mi++)
#pragma unroll
                for (int ni = 0; ni < 4; ni++)
                    mma16816(acc[mi][ni], al[mi], bh[ni]);
            if (TERMS == 3) {
#pragma unroll
                for (int mi = 0; mi < 2; mi++)
#pragma unroll
                    for (int ni = 0; ni < 4; ni++)
                        mma16816(acc[mi][ni], ah[mi], bl[ni]);
            }
        }
        if (i + 1 < nch) {
            if (i + 2 < nch)
                asm volatile("cp.async.wait_group %0;" :: "n"(1) : "memory");
            else
                asm volatile("cp.async.wait_group %0;" :: "n"(0) : "memory");
            __syncthreads();
        }
    }

#pragma unroll
    for (int mi = 0; mi < 2; mi++) {
#pragma unroll
        for (int ni = 0; ni < 4; ni++) {
            const int ch = m0 + wn * 32 + ni * 8 + lc;
            float b0 = 0.f, b1 = 0.f;
            if (MODE != 3) { b0 = __ldg(bias + ch); b1 = __ldg(bias + ch + 1); }
#pragma unroll
            for (int hh = 0; hh < 2; hh++) {
                const int pix = n0 + wm * 32 + mi * 16 + lr + hh * 8;
                const size_t prow = (size_t)b * HWSZ + pix;
                float v0 = acc[mi][ni][hh * 2] * INVWS + b0;
                float v1 = acc[mi][ni][hh * 2 + 1] * INVWS + b1;
                float2 vv; vv.x = v0; vv.y = v1;
                *(float2*)(outf + prow * (size_t)Mtot + ch) = vv;
                if (MODE == 0) {
                    size_t o = prow * 512 + ch;
                    f16 h0, l0, h1, l1;
                    hsplit(v0, &h0, &l0);
                    hsplit(v1, &h1, &l1);
                    *(__half2*)(oh + o) = __halves2half2(h0, h1);
                    *(__half2*)(ol + o) = __halves2half2(l0, l1);
                }
            }
        }
    }
}

// ---------------- attention scores (reads q,k from fused qkv) -------------
__global__ __launch_bounds__(256)
void scores_kernel(const float* __restrict__ qkv, float* __restrict__ attn) {
    extern __shared__ float sm[];
    float* Qs = sm;
    float* Ks = sm + 96 * 64;
    const int fix = blockIdx.x, dir = blockIdx.y, b = blockIdx.z;
    const int tid = threadIdx.x;
    for (int idx = tid; idx < 96 * 32; idx += 256) {
        int p = idx >> 5, f = idx & 31;
        size_t row = (size_t)b * HWSZ + (dir == 0 ? p * IMG + fix : fix * IMG + p);
        float4 v = *(const float4*)&qkv[row * 640 + f * 4];
        if (f < 16) *(float4*)&Qs[p * 64 + f * 4] = v;
        else        *(float4*)&Ks[p * 68 + (f - 16) * 4] = v;
    }
    __syncthreads();
    for (int idx = tid; idx < 9216; idx += 256) {
        int p = idx / 96, r = idx - p * 96;
        const float* qp = &Qs[p * 64];
        const float* kp = &Ks[r * 68];
        float a0 = 0.f, a1 = 0.f, a2 = 0.f, a3 = 0.f;
#pragma unroll
        for (int t = 0; t < 16; t++) {
            float4 a = *(const float4*)&qp[t * 4];
            float4 k = *(const float4*)&kp[t * 4];
            a0 += a.x * k.x; a1 += a.y * k.y; a2 += a.z * k.z; a3 += a.w * k.w;
        }
        float val = (a0 + a1) + (a2 + a3);
        if (dir == 0 && r == p) val = -1e30f;
        size_t o = (dir == 0)
            ? ((size_t)b * HWSZ + p * IMG + fix) * 192 + r
            : ((size_t)b * HWSZ + fix * IMG + p) * 192 + 96 + r;
        attn[o] = val;
    }
}

__global__ __launch_bounds__(256)
void softmax_kernel(float* __restrict__ attn) {
    const int warp = threadIdx.x >> 5, lane = threadIdx.x & 31;
    const int pix = blockIdx.x * 8 + warp;
    float* p = attn + (size_t)pix * 192;
    float v[6];
#pragma unroll
    for (int t = 0; t < 6; t++) v[t] = p[lane + 32 * t];
    float m = v[0];
#pragma unroll
    for (int t = 1; t < 6; t++) m = fmaxf(m, v[t]);
#pragma unroll
    for (int off = 16; off > 0; off >>= 1) m = fmaxf(m, __shfl_xor_sync(0xffffffffu, m, off));
    float s = 0.f;
#pragma unroll
    for (int t = 0; t < 6; t++) { v[t] = __expf(v[t] - m); s += v[t]; }
#pragma unroll
    for (int off = 16; off > 0; off >>= 1) s += __shfl_xor_sync(0xffffffffu, s, off);
    float inv = 1.f / s;
#pragma unroll
    for (int t = 0; t < 6; t++) p[lane + 32 * t] = v[t] * inv;
}

// ---------------- aggregation via tensor cores ----------------------------
// DIR=0 (h-dir, fixed w): acc[(h,w)][c] = sum_i attn_h[(h,w)][i] * V[(i,w)][c]
// DIR=1 (w-dir, fixed h): out = gamma*(accw + accb) + zin, emits zout + f16 hi/lo
// Block: 256 thr / 8 warps. M=96 (moving coord), N=128 (c chunk), K=96.
// A: attn fp16 [96][104]; B: V^T fp16 hi/lo [128][104] (2-term for V accuracy).
#define AG_SMEM 73216
template <int DIR>
__global__ __launch_bounds__(256, 2)
void agg_mma(const float* __restrict__ qkv, const float* __restrict__ attn,
             float* __restrict__ accb, const float* __restrict__ zin,
             const float* __restrict__ gamma, float* __restrict__ zout,
             f16* __restrict__ zh, f16* __restrict__ zl)
{
    extern __shared__ char smem[];
    f16* As = (f16*)smem;                       // [96][104]
    f16* Vh = (f16*)(smem + 19968);             // [128][104]
    f16* Vl = (f16*)(smem + 19968 + 26624);     // [128][104]
    const int fix = blockIdx.x, c0 = blockIdx.y * 128, b = blockIdx.z;
    const int tid = threadIdx.x, wid = tid >> 5, lane = tid & 31;

    for (int idx = tid; idx < 96 * 96; idx += 256) {
        int m = idx / 96, k = idx - m * 96;
        int pix = (DIR == 0) ? (m * IMG + fix) : (fix * IMG + m);
        As[m * 104 + k] = __float2half(attn[((size_t)b * HWSZ + pix) * 192 + DIR * 96 + k]);
    }
    for (int idx = tid; idx < 96 * 128; idx += 256) {
        int k = idx >> 7, c = idx & 127;
        int pix = (DIR == 0) ? (k * IMG + fix) : (fix * IMG + k);
        float v = qkv[((size_t)b * HWSZ + pix) * 640 + 128 + c0 + c];
        f16 hh = __float2half(v);
        Vh[c * 104 + k] = hh;
        Vl[c * 104 + k] = __float2half(v - __half2float(hh));
    }
    __syncthreads();

    const uint32_t pA = s2u(As), pVh = s2u(Vh), pVl = s2u(Vl);
    const int mq = lane >> 3, rowin = lane & 7;
    const int lr = lane >> 2, lc = (lane & 3) * 2;

    float acc[6][2][4];
#pragma unroll
    for (int mi = 0; mi < 6; mi++)
#pragma unroll
        for (int ni = 0; ni < 2; ni++)
#pragma unroll
            for (int r = 0; r < 4; r++) acc[mi][ni][r] = 0.f;

#pragma unroll
    for (int ks = 0; ks < 6; ks++) {
        uint32_t a[6][4], bh[4], bl[4];
        const int acol = ks * 16 + (mq >> 1) * 8;
#pragma unroll
        for (int mi = 0; mi < 6; mi++) {
            int row = mi * 16 + (mq & 1) * 8 + rowin;
            ldm_x4(a[mi], pA + (uint32_t)(row * 104 + acol) * 2);
        }
        {
            int n = wid * 16 + (mq >> 1) * 8 + rowin;
            int col = ks * 16 + (mq & 1) * 8;
            ldm_x4(bh, pVh + (uint32_t)(n * 104 + col) * 2);
            ldm_x4(bl, pVl + (uint32_t)(n * 104 + col) * 2);
        }
#pragma unroll
        for (int mi = 0; mi < 6; mi++) {
            mma16816(acc[mi][0], a[mi], bh);
            mma16816(acc[mi][1], a[mi], bh + 2);
        }
#pragma unroll
        for (int mi = 0; mi < 6; mi++) {
            mma16816(acc[mi][0], a[mi], bl);
            mma16816(acc[mi][1], a[mi], bl + 2);
        }
    }

    const float g = (DIR == 1) ? gamma[0] : 0.f;
#pragma unroll
    for (int mi = 0; mi < 6; mi++) {
#pragma unroll
        for (int ni = 0; ni < 2; ni++) {
            const int c = c0 + wid * 16 + ni * 8 + lc;
#pragma unroll
            for (int hh = 0; hh < 2; hh++) {
                const int m = mi * 16 + lr + hh * 8;
                const int pix = (DIR == 0) ? (m * IMG + fix) : (fix * IMG + m);
                const size_t o = ((size_t)b * HWSZ + pix) * 512 + c;
                float v0 = acc[mi][ni][hh * 2];
                float v1 = acc[mi][ni][hh * 2 + 1];
                if (DIR == 0) {
                    accb[o] = v0;
                    accb[o + 1] = v1;
                } else {
                    float w0 = g * (v0 + accb[o]) + zin[o];
                    float w1 = g * (v1 + accb[o + 1]) + zin[o + 1];
                    zout[o] = w0;
                    zout[o + 1] = w1;
                    f16 h0, l0, h1, l1;
                    hsplit(w0, &h0, &l0);
                    hsplit(w1, &h1, &l1);
                    *(__half2*)(zh + o) = __halves2half2(h0, h1);
                    *(__half2*)(zl + o) = __halves2half2(l0, l1);
                }
            }
        }
    }
}

// ---------------- GroupNorm ----------------
__global__ __launch_bounds__(256)
void gn_stats_cl(const float* __restrict__ x, float* __restrict__ stat) {
    const int b = blockIdx.x >> 5, gg = blockIdx.x & 31;
    const float* base = x + (size_t)b * HWSZ * 512 + gg * 16;
    float s = 0.f, ss = 0.f;
    for (int idx = threadIdx.x; idx < HWSZ * 4; idx += 256) {
        int pix = idx >> 2, q = idx & 3;
        float4 v = *(const float4*)(base + (size_t)pix * 512 + q * 4);
        s  += (v.x + v.y) + (v.z + v.w);
        ss += (v.x*v.x + v.y*v.y) + (v.z*v.z + v.w*v.w);
    }
    __shared__ float rs[8], rss[8];
    const int lane = threadIdx.x & 31, warp = threadIdx.x >> 5;
#pragma unroll
    for (int off = 16; off > 0; off >>= 1) {
        s  += __shfl_xor_sync(0xffffffffu, s, off);
        ss += __shfl_xor_sync(0xffffffffu, ss, off);
    }
    if (lane == 0) { rs[warp] = s; rss[warp] = ss; }
    __syncthreads();
    if (threadIdx.x == 0) {
        float S = 0.f, SS = 0.f;
#pragma unroll
        for (int i = 0; i < 8; i++) { S += rs[i]; SS += rss[i]; }
        float mean = S / 147456.f;
        float var = SS / 147456.f - mean * mean;
        stat[2 * blockIdx.x] = mean;
        stat[2 * blockIdx.x + 1] = rsqrtf(var + 1e-5f);
    }
}

__global__ __launch_bounds__(256)
void gn_out_kernel(const float* __restrict__ cl, const float* __restrict__ gam,
                   const float* __restrict__ bet, const float* __restrict__ stat,
                   float* __restrict__ out) {
    __shared__ float t[32][33];
    const int p0 = blockIdx.x * 32, c0 = blockIdx.y * 32, b = blockIdx.z;
    const int tx = threadIdx.x & 31, ty = threadIdx.x >> 5;
#pragma unroll
    for (int k = 0; k < 4; k++) {
        int pl = ty + k * 8;
        t[pl][tx] = cl[((size_t)b * HWSZ + p0 + pl) * 512 + c0 + tx];
    }
    __syncthreads();
#pragma unroll
    for (int k = 0; k < 4; k++) {
        int c = c0 + ty + k * 8;
        int sg = b * 32 + (c >> 4);
        float sc = stat[2 * sg + 1] * gam[c];
        float sh = bet[c] - stat[2 * sg] * sc;
        out[((size_t)b * 512 + c) * HWSZ + p0 + tx] = t[tx][ty + k * 8] * sc + sh;
    }
}

// ---------------- launch ----------------
extern "C" void kernel_launch(void* const* d_in, const int* in_sizes, int n_in,
                              void* d_out, int out_size) {
    const float* x   = (const float*)d_in[0];
    const float* c1w = (const float*)d_in[1];
    const float* c1b = (const float*)d_in[2];
    const float* qw  = (const float*)d_in[3];
    const float* qb  = (const float*)d_in[4];
    const float* kw  = (const float*)d_in[5];
    const float* kb  = (const float*)d_in[6];
    const float* vw  = (const float*)d_in[7];
    const float* vb  = (const float*)d_in[8];
    const float* gam = (const float*)d_in[9];
    const float* cow = (const float*)d_in[10];
    const float* gng = (const float*)d_in[11];
    const float* gnb = (const float*)d_in[12];
    float* out = (float*)d_out;

    void *p;
#define SYM(var, sym) cudaGetSymbolAddress(&p, sym); auto* var = (decltype(&sym[0]))p;
    SYM(xh, g_xh) SYM(xl, g_xl) SYM(zh, g_zh) SYM(zl, g_zl)
    SYM(z, g_z) SYM(z2, g_z2) SYM(qkv, g_qkv)
    SYM(attn, g_attn) SYM(acc, g_acc) SYM(cl, g_cl)
    SYM(c1h, g_c1h) SYM(c1l, g_c1l) SYM(qvh, g_qvh) SYM(qvl, g_qvl)
    SYM(w9h, g_w9h) SYM(w9l, g_w9l)
    SYM(bqv, g_bqv) SYM(st, g_stat)
#undef SYM

    const int SC_SM = 50688;
    cudaFuncSetAttribute(scores_kernel, cudaFuncAttributeMaxDynamicSharedMemorySize, SC_SM);
    cudaFuncSetAttribute(agg_mma<0>, cudaFuncAttributeMaxDynamicSharedMemorySize, AG_SMEM);
    cudaFuncSetAttribute(agg_mma<1>, cudaFuncAttributeMaxDynamicSharedMemorySize, AG_SMEM);
    cudaFuncSetAttribute(mma_gemm<0>, cudaFuncAttributeMaxDynamicSharedMemorySize, MG_SMEM);
    cudaFuncSetAttribute(mma_gemm<2>, cudaFuncAttributeMaxDynamicSharedMemorySize, MG_SMEM);
    cudaFuncSetAttribute(mma_gemm<3>, cudaFuncAttributeMaxDynamicSharedMemorySize, MG_SMEM);

    split_x<<<dim3(288, 64, 2), 256>>>(x, xh, xl);
    split_weights<<<(C1SZ + QVSZ + W9SZ + 255) / 256, 256>>>(
        c1w, qw, kw, vw, qb, kb, vb, cow, c1h, c1l, qvh, qvl, w9h, w9l, bqv);

    mma_gemm<0><<<dim3(72, 4, 2), 512, MG_SMEM>>>(xh, xl, c1h, c1l, c1b, z, zh, zl, 2048, 512);

    for (int it = 0; it < 2; it++) {
        float* zi = it ? z2 : z;
        float* zo = it ? z : z2;
        mma_gemm<2><<<dim3(72, 5, 2), 512, MG_SMEM>>>(zh, zl, qvh, qvl, bqv, qkv, nullptr, nullptr, 512, 640);
        scores_kernel<<<dim3(96, 2, 2), 256, SC_SM>>>(qkv, attn);
        softmax_kernel<<<2304, 256>>>(attn);
        agg_mma<0><<<dim3(96, 4, 2), 256, AG_SMEM>>>(qkv, attn, acc, nullptr, nullptr, nullptr, nullptr, nullptr);
        agg_mma<1><<<dim3(96, 4, 2), 256, AG_SMEM>>>(qkv, attn, acc, zi, gam, zo, zh, zl);
    }

    mma_gemm<3><<<dim3(72, 4, 2), 512, MG_SMEM>>>(zh, zl, w9h, w9l, nullptr, cl, nullptr, nullptr, 512, 512);
    gn_stats_cl<<<64, 256>>>(cl, st);
    gn_out_kernel<<<dim3(288, 16, 2), 256>>>(cl, gng, gnb, st, out);
}

// round 15
// speedup vs baseline: 1.3931x; 1.0309x over previous
#include <cuda_runtime.h>
#include <cuda_fp16.h>
#include <cstdint>

#define HWSZ 9216
#define IMG  96
typedef __half f16;

// ---------------- device scratch ----------------
__device__ f16 g_xh[2 * HWSZ * 2048];
__device__ f16 g_zh[2 * HWSZ * 512];
__device__ float g_z   [2 * HWSZ * 512];
__device__ float g_z2  [2 * HWSZ * 512];
__device__ float g_qkv [2 * HWSZ * 640];   // [q 0:64 | k 64:128 | v 128:640]
__device__ float g_attn[2 * HWSZ * 192];
__device__ float g_acc [2 * HWSZ * 512];
__device__ float g_cl  [2 * HWSZ * 512];
__device__ f16 g_c1h[512 * 2048], g_c1l[512 * 2048];
__device__ f16 g_qvh[640 * 512],  g_qvl[640 * 512];
__device__ f16 g_w9h[9 * 512 * 512], g_w9l[9 * 512 * 512];
__device__ float g_bqv[640];
__device__ float g_stat[128];

#define WSCALE 64.0f
#define INVWS  0.015625f

// ---------------- helpers ----------------
__device__ __forceinline__ uint32_t s2u(const void* p) {
    uint32_t a;
    asm("{ .reg .u64 t; cvta.to.shared.u64 t, %1; cvt.u32.u64 %0, t; }" : "=r"(a) : "l"(p));
    return a;
}
__device__ __forceinline__ void hsplit(float v, f16* h, f16* l) {
    f16 hh = __float2half(v);
    *h = hh;
    *l = __float2half(v - __half2float(hh));
}
__device__ __forceinline__ void mma16816(float* d, const uint32_t* a, const uint32_t* b) {
    asm volatile(
        "mma.sync.aligned.m16n8k16.row.col.f32.f16.f16.f32 "
        "{%0,%1,%2,%3}, {%4,%5,%6,%7}, {%8,%9}, {%0,%1,%2,%3};"
        : "+f"(d[0]), "+f"(d[1]), "+f"(d[2]), "+f"(d[3])
        : "r"(a[0]), "r"(a[1]), "r"(a[2]), "r"(a[3]), "r"(b[0]), "r"(b[1]));
}
__device__ __forceinline__ void cpasync16(uint32_t s, const void* g) {
    asm volatile("cp.async.cg.shared.global [%0], [%1], 16;" :: "r"(s), "l"(g));
}
__device__ __forceinline__ void ldm_x4(uint32_t* r, uint32_t addr) {
    asm volatile("ldmatrix.sync.aligned.m8n8.x4.shared.b16 {%0,%1,%2,%3}, [%4];"
                 : "=r"(r[0]), "=r"(r[1]), "=r"(r[2]), "=r"(r[3]) : "r"(addr));
}

// ---------------- x -> fp16 channel-last (single copy) ----------------
__global__ void conv_x(const float* __restrict__ x, f16* __restrict__ xh) {
    __shared__ float t[32][33];
    const int p0 = blockIdx.x * 32, c0 = blockIdx.y * 32, b = blockIdx.z;
    const int tx = threadIdx.x & 31, ty = threadIdx.x >> 5;
#pragma unroll
    for (int k = 0; k < 4; k++) {
        int cc = ty + k * 8;
        t[cc][tx] = x[((size_t)b * 2048 + c0 + cc) * HWSZ + p0 + tx];
    }
    __syncthreads();
#pragma unroll
    for (int k = 0; k < 4; k++) {
        int pl = ty + k * 8;
        size_t o = ((size_t)b * HWSZ + p0 + pl) * 2048 + c0 + tx;
        xh[o] = __float2half(t[tx][pl]);
    }
}

#define C1SZ  (512 * 2048)
#define QVSZ  (640 * 512)
#define W9SZ  (9 * 512 * 512)
__global__ void split_weights(const float* __restrict__ c1w,
                              const float* __restrict__ qw, const float* __restrict__ kw,
                              const float* __restrict__ vw, const float* __restrict__ qb,
                              const float* __restrict__ kb, const float* __restrict__ vb,
                              const float* __restrict__ cow,
                              f16* __restrict__ c1h, f16* __restrict__ c1l,
                              f16* __restrict__ qvh, f16* __restrict__ qvl,
                              f16* __restrict__ w9h, f16* __restrict__ w9l,
                              float* __restrict__ bqv) {
    int i = blockIdx.x * 256 + threadIdx.x;
    if (i < 640)
        bqv[i] = (i < 64) ? qb[i] : (i < 128) ? kb[i - 64] : vb[i - 128];
    if (i < C1SZ) {
        hsplit(WSCALE * c1w[i], &c1h[i], &c1l[i]);
    } else if (i < C1SZ + QVSZ) {
        int j = i - C1SZ;
        int m = j >> 9, k = j & 511;
        float v = (m < 64) ? qw[m * 512 + k]
                : (m < 128) ? kw[(m - 64) * 512 + k]
                            : vw[(m - 128) * 512 + k];
        hsplit(WSCALE * v, &qvh[j], &qvl[j]);
    } else if (i < C1SZ + QVSZ + W9SZ) {
        int d = i - C1SZ - QVSZ;
        int s = d / (512 * 512), r = d % (512 * 512);
        int o = r >> 9, ic = r & 511;
        hsplit(WSCALE * cow[(o * 512 + ic) * 9 + s], &w9h[d], &w9l[d]);
    }
}

// ---------------- 2-term GEMM: A single fp16, B split hi/lo ---------------
// D = (1/64)*(A . (64B)^T) + bias ; terms A*Bh + A*Bl
// MODE 0: conv1 (z fp32 + zh fp16), 2: qkv (fp32), 3: conv3 (9 shifts)
#define OPSZ 5120
#define OPB  10240
#define BUFE 15360           // 3 operands per stage
#define BUFB 30720
#define NSTG 3
#define MG_SMEM (4864 + NSTG * BUFB)
template <int MODE>
__global__ __launch_bounds__(512, 1)
void mma_gemm(const f16* __restrict__ A, const f16* __restrict__ Bh,
              const f16* __restrict__ Bl, const float* __restrict__ bias,
              float* __restrict__ outf, f16* __restrict__ oh,
              int K, int Mtot)
{
    extern __shared__ char smem[];
    int* srcn = (int*)smem;
    f16* tiles = (f16*)(smem + 4864);
    const uint32_t smbase = s2u(tiles);
    const int tid = threadIdx.x, wid = tid >> 5, lane = tid & 31;
    const int n0 = blockIdx.x * 128, m0 = blockIdx.y * 128, b = blockIdx.z;

    if (MODE == 3 && tid < 128) {
        int n = n0 + tid, y = n / IMG, x = n - y * IMG;
#pragma unroll
        for (int s = 0; s < 9; s++) {
            int sy = y + s / 3 - 1, sx = x + s % 3 - 1;
            srcn[s * 128 + tid] = (sy >= 0 && sy < IMG && sx >= 0 && sx < IMG) ? sy * IMG + sx : -1;
        }
    }
    __syncthreads();

    // loaders: g<2 (256 thr) -> A ; g==2 -> Bh ; g==3 -> Bl
    const int g = tid >> 7, u = tid & 127;
    const int nch = (MODE == 3) ? 144 : (K >> 5);

    auto load_chunk = [&](int i) {
        f16* t = tiles + (i % NSTG) * BUFE;
        int s = 0, k0;
        if (MODE == 3) { s = i >> 4; k0 = (i & 15) << 5; } else { k0 = i << 5; }
        if (g < 2) {
            const int tt = (g << 7) | u, qq = tt & 3, rr = tt >> 2;
#pragma unroll
            for (int j = 0; j < 2; j++) {
                int row = rr + j * 64;
                uint32_t sa = s2u(t + row * 40 + qq * 8);
                long rn = -1;
                if (MODE == 3) { int sn = srcn[s * 128 + row]; if (sn >= 0) rn = sn; }
                else rn = n0 + row;
                if (rn >= 0)
                    cpasync16(sa, A + ((size_t)b * HWSZ + rn) * (size_t)K + k0 + qq * 8);
                else
                    *(uint4*)(t + row * 40 + qq * 8) = make_uint4(0, 0, 0, 0);
            }
        } else {
            const f16* srcp = (g == 2) ? Bh : Bl;
            f16* td = t + (g - 1) * OPSZ;
            const int qq = u & 3, rr = u >> 2;
#pragma unroll
            for (int j = 0; j < 4; j++) {
                int row = rr + j * 32;
                uint32_t sa = s2u(td + row * 40 + qq * 8);
                size_t mrow = (MODE == 3) ? ((size_t)s * 512 + m0 + row) : (size_t)(m0 + row);
                cpasync16(sa, srcp + mrow * (size_t)K + k0 + qq * 8);
            }
        }
        asm volatile("cp.async.commit_group;" ::: "memory");
    };

    float acc[2][4][4];
#pragma unroll
    for (int mi = 0; mi < 2; mi++)
#pragma unroll
        for (int ni = 0; ni < 4; ni++)
#pragma unroll
            for (int r = 0; r < 4; r++) acc[mi][ni][r] = 0.f;

    const int wm = wid >> 2, wn = wid & 3;
    const int lr = lane >> 2, lc = (lane & 3) * 2;
    const int mq = lane >> 3, rowin = lane & 7;

    uint32_t aoff[2][2], boff[2][2];
#pragma unroll
    for (int ks = 0; ks < 2; ks++) {
#pragma unroll
        for (int mi = 0; mi < 2; mi++) {
            int row = wm * 32 + mi * 16 + (mq & 1) * 8 + rowin;
            int col = ks * 16 + (mq >> 1) * 8;
            aoff[ks][mi] = (uint32_t)(row * 40 + col) * 2;
        }
#pragma unroll
        for (int np = 0; np < 2; np++) {
            int n = wn * 32 + np * 16 + (mq >> 1) * 8 + rowin;
            int col = ks * 16 + (mq & 1) * 8;
            boff[ks][np] = (uint32_t)(n * 40 + col) * 2;
        }
    }

    load_chunk(0);
    if (nch > 1) load_chunk(1);
    asm volatile("cp.async.wait_group %0;" :: "n"(1) : "memory");
    __syncthreads();

    for (int i = 0; i < nch; i++) {
        if (i + 2 < nch) load_chunk(i + 2);
        const uint32_t tb = smbase + (i % NSTG) * BUFB;
        const uint32_t pA = tb, pBh = tb + OPB, pBl = tb + 2 * OPB;
#pragma unroll
        for (int ks = 0; ks < 2; ks++) {
            uint32_t ah[2][4], bh[4][2], bl[4][2], tmp[4];
#pragma unroll
            for (int mi = 0; mi < 2; mi++)
                ldm_x4(ah[mi], pA + aoff[ks][mi]);
#pragma unroll
            for (int np = 0; np < 2; np++) {
                ldm_x4(tmp, pBh + boff[ks][np]);
                bh[2*np][0] = tmp[0]; bh[2*np][1] = tmp[1];
                bh[2*np+1][0] = tmp[2]; bh[2*np+1][1] = tmp[3];
                ldm_x4(tmp, pBl + boff[ks][np]);
                bl[2*np][0] = tmp[0]; bl[2*np][1] = tmp[1];
                bl[2*np+1][0] = tmp[2]; bl[2*np+1][1] = tmp[3];
            }
#pragma unroll
            for (int mi = 0; mi < 2; mi++)
#pragma unroll
                for (int ni = 0; ni < 4; ni++)
                    mma16816(acc[mi][ni], ah[mi], bh[ni]);
#pragma unroll
            for (int mi = 0; mi < 2; mi++)
#pragma unroll
                for (int ni = 0; ni < 4; ni++)
                    mma16816(acc[mi][ni], ah[mi], bl[ni]);
        }
        if (i + 1 < nch) {
            if (i + 2 < nch)
                asm volatile("cp.async.wait_group %0;" :: "n"(1) : "memory");
            else
                asm volatile("cp.async.wait_group %0;" :: "n"(0) : "memory");
            __syncthreads();
        }
    }

#pragma unroll
    for (int mi = 0; mi < 2; mi++) {
#pragma unroll
        for (int ni = 0; ni < 4; ni++) {
            const int ch = m0 + wn * 32 + ni * 8 + lc;
            float b0 = 0.f, b1 = 0.f;
            if (MODE != 3) { b0 = __ldg(bias + ch); b1 = __ldg(bias + ch + 1); }
#pragma unroll
            for (int hh = 0; hh < 2; hh++) {
                const int pix = n0 + wm * 32 + mi * 16 + lr + hh * 8;
                const size_t prow = (size_t)b * HWSZ + pix;
                float v0 = acc[mi][ni][hh * 2] * INVWS + b0;
                float v1 = acc[mi][ni][hh * 2 + 1] * INVWS + b1;
                float2 vv; vv.x = v0; vv.y = v1;
                *(float2*)(outf + prow * (size_t)Mtot + ch) = vv;
                if (MODE == 0) {
                    size_t o = prow * 512 + ch;
                    *(__half2*)(oh + o) = __halves2half2(__float2half(v0), __float2half(v1));
                }
            }
        }
    }
}

// ---------------- attention scores ----------------
__global__ __launch_bounds__(256)
void scores_kernel(const float* __restrict__ qkv, float* __restrict__ attn) {
    extern __shared__ float sm[];
    float* Qs = sm;
    float* Ks = sm + 96 * 64;
    const int fix = blockIdx.x, dir = blockIdx.y, b = blockIdx.z;
    const int tid = threadIdx.x;
    for (int idx = tid; idx < 96 * 32; idx += 256) {
        int p = idx >> 5, f = idx & 31;
        size_t row = (size_t)b * HWSZ + (dir == 0 ? p * IMG + fix : fix * IMG + p);
        float4 v = *(const float4*)&qkv[row * 640 + f * 4];
        if (f < 16) *(float4*)&Qs[p * 64 + f * 4] = v;
        else        *(float4*)&Ks[p * 68 + (f - 16) * 4] = v;
    }
    __syncthreads();
    for (int idx = tid; idx < 9216; idx += 256) {
        int p = idx / 96, r = idx - p * 96;
        const float* qp = &Qs[p * 64];
        const float* kp = &Ks[r * 68];
        float a0 = 0.f, a1 = 0.f, a2 = 0.f, a3 = 0.f;
#pragma unroll
        for (int t = 0; t < 16; t++) {
            float4 a = *(const float4*)&qp[t * 4];
            float4 k = *(const float4*)&kp[t * 4];
            a0 += a.x * k.x; a1 += a.y * k.y; a2 += a.z * k.z; a3 += a.w * k.w;
        }
        float val = (a0 + a1) + (a2 + a3);
        if (dir == 0 && r == p) val = -1e30f;
        size_t o = (dir == 0)
            ? ((size_t)b * HWSZ + p * IMG + fix) * 192 + r
            : ((size_t)b * HWSZ + fix * IMG + p) * 192 + 96 + r;
        attn[o] = val;
    }
}

__global__ __launch_bounds__(256)
void softmax_kernel(float* __restrict__ attn) {
    const int warp = threadIdx.x >> 5, lane = threadIdx.x & 31;
    const int pix = blockIdx.x * 8 + warp;
    float* p = attn + (size_t)pix * 192;
    float v[6];
#pragma unroll
    for (int t = 0; t < 6; t++) v[t] = p[lane + 32 * t];
    float m = v[0];
#pragma unroll
    for (int t = 1; t < 6; t++) m = fmaxf(m, v[t]);
#pragma unroll
    for (int off = 16; off > 0; off >>= 1) m = fmaxf(m, __shfl_xor_sync(0xffffffffu, m, off));
    float s = 0.f;
#pragma unroll
    for (int t = 0; t < 6; t++) { v[t] = __expf(v[t] - m); s += v[t]; }
#pragma unroll
    for (int off = 16; off > 0; off >>= 1) s += __shfl_xor_sync(0xffffffffu, s, off);
    float inv = 1.f / s;
#pragma unroll
    for (int t = 0; t < 6; t++) p[lane + 32 * t] = v[t] * inv;
}

// ---------------- aggregation via tensor cores (V single fp16) ------------
#define AG_SMEM 46592
template <int DIR>
__global__ __launch_bounds__(256, 2)
void agg_mma(const float* __restrict__ qkv, const float* __restrict__ attn,
             float* __restrict__ accb, const float* __restrict__ zin,
             const float* __restrict__ gamma, float* __restrict__ zout,
             f16* __restrict__ zh)
{
    extern __shared__ char smem[];
    f16* As = (f16*)smem;                       // [96][104]
    f16* Vh = (f16*)(smem + 19968);             // [128][104]
    const int fix = blockIdx.x, c0 = blockIdx.y * 128, b = blockIdx.z;
    const int tid = threadIdx.x, wid = tid >> 5, lane = tid & 31;

    for (int idx = tid; idx < 96 * 96; idx += 256) {
        int m = idx / 96, k = idx - m * 96;
        int pix = (DIR == 0) ? (m * IMG + fix) : (fix * IMG + m);
        As[m * 104 + k] = __float2half(attn[((size_t)b * HWSZ + pix) * 192 + DIR * 96 + k]);
    }
    for (int idx = tid; idx < 96 * 128; idx += 256) {
        int k = idx >> 7, c = idx & 127;
        int pix = (DIR == 0) ? (k * IMG + fix) : (fix * IMG + k);
        Vh[c * 104 + k] = __float2half(qkv[((size_t)b * HWSZ + pix) * 640 + 128 + c0 + c]);
    }
    __syncthreads();

    const uint32_t pA = s2u(As), pVh = s2u(Vh);
    const int mq = lane >> 3, rowin = lane & 7;
    const int lr = lane >> 2, lc = (lane & 3) * 2;

    float acc[6][2][4];
#pragma unroll
    for (int mi = 0; mi < 6; mi++)
#pragma unroll
        for (int ni = 0; ni < 2; ni++)
#pragma unroll
            for (int r = 0; r < 4; r++) acc[mi][ni][r] = 0.f;

#pragma unroll
    for (int ks = 0; ks < 6; ks++) {
        uint32_t a[6][4], bh[4];
        const int acol = ks * 16 + (mq >> 1) * 8;
#pragma unroll
        for (int mi = 0; mi < 6; mi++) {
            int row = mi * 16 + (mq & 1) * 8 + rowin;
            ldm_x4(a[mi], pA + (uint32_t)(row * 104 + acol) * 2);
        }
        {
            int n = wid * 16 + (mq >> 1) * 8 + rowin;
            int col = ks * 16 + (mq & 1) * 8;
            ldm_x4(bh, pVh + (uint32_t)(n * 104 + col) * 2);
        }
#pragma unroll
        for (int mi = 0; mi < 6; mi++) {
            mma16816(acc[mi][0], a[mi], bh);
            mma16816(acc[mi][1], a[mi], bh + 2);
        }
    }

    const float g = (DIR == 1) ? gamma[0] : 0.f;
#pragma unroll
    for (int mi = 0; mi < 6; mi++) {
#pragma unroll
        for (int ni = 0; ni < 2; ni++) {
            const int c = c0 + wid * 16 + ni * 8 + lc;
#pragma unroll
            for (int hh = 0; hh < 2; hh++) {
                const int m = mi * 16 + lr + hh * 8;
                const int pix = (DIR == 0) ? (m * IMG + fix) : (fix * IMG + m);
                const size_t o = ((size_t)b * HWSZ + pix) * 512 + c;
                float v0 = acc[mi][ni][hh * 2];
                float v1 = acc[mi][ni][hh * 2 + 1];
                if (DIR == 0) {
                    accb[o] = v0;
                    accb[o + 1] = v1;
                } else {
                    float w0 = g * (v0 + accb[o]) + zin[o];
                    float w1 = g * (v1 + accb[o + 1]) + zin[o + 1];
                    zout[o] = w0;
                    zout[o + 1] = w1;
                    *(__half2*)(zh + o) = __halves2half2(__float2half(w0), __float2half(w1));
                }
            }
        }
    }
}

// ---------------- GroupNorm ----------------
__global__ __launch_bounds__(256)
void gn_stats_cl(const float* __restrict__ x, float* __restrict__ stat) {
    const int b = blockIdx.x >> 5, gg = blockIdx.x & 31;
    const float* base = x + (size_t)b * HWSZ * 512 + gg * 16;
    float s = 0.f, ss = 0.f;
    for (int idx = threadIdx.x; idx < HWSZ * 4; idx += 256) {
        int pix = idx >> 2, q = idx & 3;
        float4 v = *(const float4*)(base + (size_t)pix * 512 + q * 4);
        s  += (v.x + v.y) + (v.z + v.w);
        ss += (v.x*v.x + v.y*v.y) + (v.z*v.z + v.w*v.w);
    }
    __shared__ float rs[8], rss[8];
    const int lane = threadIdx.x & 31, warp = threadIdx.x >> 5;
#pragma unroll
    for (int off = 16; off > 0; off >>= 1) {
        s  += __shfl_xor_sync(0xffffffffu, s, off);
        ss += __shfl_xor_sync(0xffffffffu, ss, off);
    }
    if (lane == 0) { rs[warp] = s; rss[warp] = ss; }
    __syncthreads();
    if (threadIdx.x == 0) {
        float S = 0.f, SS = 0.f;
#pragma unroll
        for (int i = 0; i < 8; i++) { S += rs[i]; SS += rss[i]; }
        float mean = S / 147456.f;
        float var = SS / 147456.f - mean * mean;
        stat[2 * blockIdx.x] = mean;
        stat[2 * blockIdx.x + 1] = rsqrtf(var + 1e-5f);
    }
}

__global__ __launch_bounds__(256)
void gn_out_kernel(const float* __restrict__ cl, const float* __restrict__ gam,
                   const float* __restrict__ bet, const float* __restrict__ stat,
                   float* __restrict__ out) {
    __shared__ float t[32][33];
    const int p0 = blockIdx.x * 32, c0 = blockIdx.y * 32, b = blockIdx.z;
    const int tx = threadIdx.x & 31, ty = threadIdx.x >> 5;
#pragma unroll
    for (int k = 0; k < 4; k++) {
        int pl = ty + k * 8;
        t[pl][tx] = cl[((size_t)b * HWSZ + p0 + pl) * 512 + c0 + tx];
    }
    __syncthreads();
#pragma unroll
    for (int k = 0; k < 4; k++) {
        int c = c0 + ty + k * 8;
        int sg = b * 32 + (c >> 4);
        float sc = stat[2 * sg + 1] * gam[c];
        float sh = bet[c] - stat[2 * sg] * sc;
        out[((size_t)b * 512 + c) * HWSZ + p0 + tx] = t[tx][ty + k * 8] * sc + sh;
    }
}

// ---------------- launch ----------------
extern "C" void kernel_launch(void* const* d_in, const int* in_sizes, int n_in,
                              void* d_out, int out_size) {
    const float* x   = (const float*)d_in[0];
    const float* c1w = (const float*)d_in[1];
    const float* c1b = (const float*)d_in[2];
    const float* qw  = (const float*)d_in[3];
    const float* qb  = (const float*)d_in[4];
    const float* kw  = (const float*)d_in[5];
    const float* kb  = (const float*)d_in[6];
    const float* vw  = (const float*)d_in[7];
    const float* vb  = (const float*)d_in[8];
    const float* gam = (const float*)d_in[9];
    const float* cow = (const float*)d_in[10];
    const float* gng = (const float*)d_in[11];
    const float* gnb = (const float*)d_in[12];
    float* out = (float*)d_out;

    void *p;
#define SYM(var, sym) cudaGetSymbolAddress(&p, sym); auto* var = (decltype(&sym[0]))p;
    SYM(xh, g_xh) SYM(zh, g_zh)
    SYM(z, g_z) SYM(z2, g_z2) SYM(qkv, g_qkv)
    SYM(attn, g_attn) SYM(acc, g_acc) SYM(cl, g_cl)
    SYM(c1h, g_c1h) SYM(c1l, g_c1l) SYM(qvh, g_qvh) SYM(qvl, g_qvl)
    SYM(w9h, g_w9h) SYM(w9l, g_w9l)
    SYM(bqv, g_bqv) SYM(st, g_stat)
#undef SYM

    const int SC_SM = 50688;
    cudaFuncSetAttribute(scores_kernel, cudaFuncAttributeMaxDynamicSharedMemorySize, SC_SM);
    cudaFuncSetAttribute(agg_mma<0>, cudaFuncAttributeMaxDynamicSharedMemorySize, AG_SMEM);
    cudaFuncSetAttribute(agg_mma<1>, cudaFuncAttributeMaxDynamicSharedMemorySize, AG_SMEM);
    cudaFuncSetAttribute(mma_gemm<0>, cudaFuncAttributeMaxDynamicSharedMemorySize, MG_SMEM);
    cudaFuncSetAttribute(mma_gemm<2>, cudaFuncAttributeMaxDynamicSharedMemorySize, MG_SMEM);
    cudaFuncSetAttribute(mma_gemm<3>, cudaFuncAttributeMaxDynamicSharedMemorySize, MG_SMEM);

    conv_x<<<dim3(288, 64, 2), 256>>>(x, xh);
    split_weights<<<(C1SZ + QVSZ + W9SZ + 255) / 256, 256>>>(
        c1w, qw, kw, vw, qb, kb, vb, cow, c1h, c1l, qvh, qvl, w9h, w9l, bqv);

    mma_gemm<0><<<dim3(72, 4, 2), 512, MG_SMEM>>>(xh, c1h, c1l, c1b, z, zh, 2048, 512);

    for (int it = 0; it < 2; it++) {
        float* zi = it ? z2 : z;
        float* zo = it ? z : z2;
        mma_gemm<2><<<dim3(72, 5, 2), 512, MG_SMEM>>>(zh, qvh, qvl, bqv, qkv, nullptr, 512, 640);
        scores_kernel<<<dim3(96, 2, 2), 256, SC_SM>>>(qkv, attn);
        softmax_kernel<<<2304, 256>>>(attn);
        agg_mma<0><<<dim3(96, 4, 2), 256, AG_SMEM>>>(qkv, attn, acc, nullptr, nullptr, nullptr, nullptr);
        agg_mma<1><<<dim3(96, 4, 2), 256, AG_SMEM>>>(qkv, attn, acc, zi, gam, zo, zh);
    }

    mma_gemm<3><<<dim3(72, 4, 2), 512, MG_SMEM>>>(zh, w9h, w9l, nullptr, cl, nullptr, 512, 512);
    gn_stats_cl<<<64, 256>>>(cl, st);
    gn_out_kernel<<<dim3(288, 16, 2), 256>>>(cl, gng, gnb, st, out);
}

// round 16
// speedup vs baseline: 1.8245x; 1.3097x over previous
#include <cuda_runtime.h>
#include <cuda_fp16.h>
#include <cstdint>

#define HWSZ 9216
#define IMG  96
typedef __half f16;

// ---------------- device scratch ----------------
__device__ f16 g_xh[2 * HWSZ * 2048];
__device__ f16 g_zh[2 * HWSZ * 512];
__device__ float g_z   [2 * HWSZ * 512];
__device__ float g_z2  [2 * HWSZ * 512];
__device__ float g_qkv [2 * HWSZ * 640];   // [q 0:64 | k 64:128 | v 128:640]
__device__ float g_attn[2 * HWSZ * 192];
__device__ float g_acc [2 * HWSZ * 512];
__device__ float g_cl  [2 * HWSZ * 512];
__device__ f16 g_c1h[512 * 2048];
__device__ f16 g_qvh[640 * 512],  g_qvl[640 * 512];
__device__ f16 g_w9h[9 * 512 * 512];
__device__ float g_bqv[640];
__device__ float g_stat[128];

#define WSCALE 64.0f
#define INVWS  0.015625f

// ---------------- helpers ----------------
__device__ __forceinline__ uint32_t s2u(const void* p) {
    uint32_t a;
    asm("{ .reg .u64 t; cvta.to.shared.u64 t, %1; cvt.u32.u64 %0, t; }" : "=r"(a) : "l"(p));
    return a;
}
__device__ __forceinline__ void hsplit(float v, f16* h, f16* l) {
    f16 hh = __float2half(v);
    *h = hh;
    *l = __float2half(v - __half2float(hh));
}
__device__ __forceinline__ void mma16816(float* d, const uint32_t* a, const uint32_t* b) {
    asm volatile(
        "mma.sync.aligned.m16n8k16.row.col.f32.f16.f16.f32 "
        "{%0,%1,%2,%3}, {%4,%5,%6,%7}, {%8,%9}, {%0,%1,%2,%3};"
        : "+f"(d[0]), "+f"(d[1]), "+f"(d[2]), "+f"(d[3])
        : "r"(a[0]), "r"(a[1]), "r"(a[2]), "r"(a[3]), "r"(b[0]), "r"(b[1]));
}
__device__ __forceinline__ void cpasync16(uint32_t s, const void* g) {
    asm volatile("cp.async.cg.shared.global [%0], [%1], 16;" :: "r"(s), "l"(g));
}
__device__ __forceinline__ void ldm_x4(uint32_t* r, uint32_t addr) {
    asm volatile("ldmatrix.sync.aligned.m8n8.x4.shared.b16 {%0,%1,%2,%3}, [%4];"
                 : "=r"(r[0]), "=r"(r[1]), "=r"(r[2]), "=r"(r[3]) : "r"(addr));
}

// ---------------- x -> fp16 channel-last ----------------
__global__ void conv_x(const float* __restrict__ x, f16* __restrict__ xh) {
    __shared__ float t[32][33];
    const int p0 = blockIdx.x * 32, c0 = blockIdx.y * 32, b = blockIdx.z;
    const int tx = threadIdx.x & 31, ty = threadIdx.x >> 5;
#pragma unroll
    for (int k = 0; k < 4; k++) {
        int cc = ty + k * 8;
        t[cc][tx] = x[((size_t)b * 2048 + c0 + cc) * HWSZ + p0 + tx];
    }
    __syncthreads();
#pragma unroll
    for (int k = 0; k < 4; k++) {
        int pl = ty + k * 8;
        size_t o = ((size_t)b * HWSZ + p0 + pl) * 2048 + c0 + tx;
        xh[o] = __float2half(t[tx][pl]);
    }
}

#define C1SZ  (512 * 2048)
#define QVSZ  (640 * 512)
#define W9SZ  (9 * 512 * 512)
__global__ void split_weights(const float* __restrict__ c1w,
                              const float* __restrict__ qw, const float* __restrict__ kw,
                              const float* __restrict__ vw, const float* __restrict__ qb,
                              const float* __restrict__ kb, const float* __restrict__ vb,
                              const float* __restrict__ cow,
                              f16* __restrict__ c1h,
                              f16* __restrict__ qvh, f16* __restrict__ qvl,
                              f16* __restrict__ w9h,
                              float* __restrict__ bqv) {
    int i = blockIdx.x * 256 + threadIdx.x;
    if (i < 640)
        bqv[i] = (i < 64) ? qb[i] : (i < 128) ? kb[i - 64] : vb[i - 128];
    if (i < C1SZ) {
        c1h[i] = __float2half(WSCALE * c1w[i]);
    } else if (i < C1SZ + QVSZ) {
        int j = i - C1SZ;
        int m = j >> 9, k = j & 511;
        float v = (m < 64) ? qw[m * 512 + k]
                : (m < 128) ? kw[(m - 64) * 512 + k]
                            : vw[(m - 128) * 512 + k];
        hsplit(WSCALE * v, &qvh[j], &qvl[j]);
    } else if (i < C1SZ + QVSZ + W9SZ) {
        int d = i - C1SZ - QVSZ;
        int s = d / (512 * 512), r = d % (512 * 512);
        int o = r >> 9, ic = r & 511;
        w9h[d] = __float2half(WSCALE * cow[(o * 512 + ic) * 9 + s]);
    }
}

// ---------------- fp16 tensor-core GEMM ----------------
// D = (1/64)*(A . (64B)^T) + bias
// TERMS = 2 (MODE 2: qkv, B split hi/lo) or 1 (MODE 0 conv1 / MODE 3 conv3)
#define OPSZ 5120
#define OPB  10240
#define BUFE 15360
#define BUFB 30720
#define NSTG 3
#define MG_SMEM (4864 + NSTG * BUFB)
template <int MODE>
__global__ __launch_bounds__(512, 1)
void mma_gemm(const f16* __restrict__ A, const f16* __restrict__ Bh,
              const f16* __restrict__ Bl, const float* __restrict__ bias,
              float* __restrict__ outf, f16* __restrict__ oh,
              int K, int Mtot)
{
    constexpr int TERMS = (MODE == 2) ? 2 : 1;
    extern __shared__ char smem[];
    int* srcn = (int*)smem;
    f16* tiles = (f16*)(smem + 4864);
    const uint32_t smbase = s2u(tiles);
    const int tid = threadIdx.x, wid = tid >> 5, lane = tid & 31;
    const int n0 = blockIdx.x * 128, m0 = blockIdx.y * 128, b = blockIdx.z;

    if (MODE == 3 && tid < 128) {
        int n = n0 + tid, y = n / IMG, x = n - y * IMG;
#pragma unroll
        for (int s = 0; s < 9; s++) {
            int sy = y + s / 3 - 1, sx = x + s % 3 - 1;
            srcn[s * 128 + tid] = (sy >= 0 && sy < IMG && sx >= 0 && sx < IMG) ? sy * IMG + sx : -1;
        }
    }
    __syncthreads();

    // loaders: g<2 (256 thr) -> A ; g==2 -> Bh ; g==3 -> Bl (idle if TERMS==1)
    const int g = tid >> 7, u = tid & 127;
    const int nch = (MODE == 3) ? 144 : (K >> 5);

    auto load_chunk = [&](int i) {
        f16* t = tiles + (i % NSTG) * BUFE;
        int s = 0, k0;
        if (MODE == 3) { s = i >> 4; k0 = (i & 15) << 5; } else { k0 = i << 5; }
        if (g < 2) {
            const int tt = (g << 7) | u, qq = tt & 3, rr = tt >> 2;
#pragma unroll
            for (int j = 0; j < 2; j++) {
                int row = rr + j * 64;
                uint32_t sa = s2u(t + row * 40 + qq * 8);
                long rn = -1;
                if (MODE == 3) { int sn = srcn[s * 128 + row]; if (sn >= 0) rn = sn; }
                else rn = n0 + row;
                if (rn >= 0)
                    cpasync16(sa, A + ((size_t)b * HWSZ + rn) * (size_t)K + k0 + qq * 8);
                else
                    *(uint4*)(t + row * 40 + qq * 8) = make_uint4(0, 0, 0, 0);
            }
        } else if (g == 2 || TERMS == 2) {
            const f16* srcp = (g == 2) ? Bh : Bl;
            f16* td = t + (g - 1) * OPSZ;
            const int qq = u & 3, rr = u >> 2;
#pragma unroll
            for (int j = 0; j < 4; j++) {
                int row = rr + j * 32;
                uint32_t sa = s2u(td + row * 40 + qq * 8);
                size_t mrow = (MODE == 3) ? ((size_t)s * 512 + m0 + row) : (size_t)(m0 + row);
                cpasync16(sa, srcp + mrow * (size_t)K + k0 + qq * 8);
            }
        }
        asm volatile("cp.async.commit_group;" ::: "memory");
    };

    float acc[2][4][4];
#pragma unroll
    for (int mi = 0; mi < 2; mi++)
#pragma unroll
        for (int ni = 0; ni < 4; ni++)
#pragma unroll
            for (int r = 0; r < 4; r++) acc[mi][ni][r] = 0.f;

    const int wm = wid >> 2, wn = wid & 3;
    const int lr = lane >> 2, lc = (lane & 3) * 2;
    const int mq = lane >> 3, rowin = lane & 7;

    uint32_t aoff[2][2], boff[2][2];
#pragma unroll
    for (int ks = 0; ks < 2; ks++) {
#pragma unroll
        for (int mi = 0; mi < 2; mi++) {
            int row = wm * 32 + mi * 16 + (mq & 1) * 8 + rowin;
            int col = ks * 16 + (mq >> 1) * 8;
            aoff[ks][mi] = (uint32_t)(row * 40 + col) * 2;
        }
#pragma unroll
        for (int np = 0; np < 2; np++) {
            int n = wn * 32 + np * 16 + (mq >> 1) * 8 + rowin;
            int col = ks * 16 + (mq & 1) * 8;
            boff[ks][np] = (uint32_t)(n * 40 + col) * 2;
        }
    }

    load_chunk(0);
    if (nch > 1) load_chunk(1);
    asm volatile("cp.async.wait_group %0;" :: "n"(1) : "memory");
    __syncthreads();

    for (int i = 0; i < nch; i++) {
        if (i + 2 < nch) load_chunk(i + 2);
        const uint32_t tb = smbase + (i % NSTG) * BUFB;
        const uint32_t pA = tb, pBh = tb + OPB, pBl = tb + 2 * OPB;
#pragma unroll
        for (int ks = 0; ks < 2; ks++) {
            uint32_t ah[2][4], bh[4][2], bl[4][2], tmp[4];
#pragma unroll
            for (int mi = 0; mi < 2; mi++)
                ldm_x4(ah[mi], pA + aoff[ks][mi]);
#pragma unroll
            for (int np = 0; np < 2; np++) {
                ldm_x4(tmp, pBh + boff[ks][np]);
                bh[2*np][0] = tmp[0]; bh[2*np][1] = tmp[1];
                bh[2*np+1][0] = tmp[2]; bh[2*np+1][1] = tmp[3];
                if (TERMS == 2) {
                    ldm_x4(tmp, pBl + boff[ks][np]);
                    bl[2*np][0] = tmp[0]; bl[2*np][1] = tmp[1];
                    bl[2*np+1][0] = tmp[2]; bl[2*np+1][1] = tmp[3];
                }
            }
#pragma unroll
            for (int mi = 0; mi < 2; mi++)
#pragma unroll
                for (int ni = 0; ni < 4; ni++)
                    mma16816(acc[mi][ni], ah[mi], bh[ni]);
            if (TERMS == 2) {
#pragma unroll
                for (int mi = 0; mi < 2; mi++)
#pragma unroll
                    for (int ni = 0; ni < 4; ni++)
                        mma16816(acc[mi][ni], ah[mi], bl[ni]);
            }
        }
        if (i + 1 < nch) {
            if (i + 2 < nch)
                asm volatile("cp.async.wait_group %0;" :: "n"(1) : "memory");
            else
                asm volatile("cp.async.wait_group %0;" :: "n"(0) : "memory");
            __syncthreads();
        }
    }

#pragma unroll
    for (int mi = 0; mi < 2; mi++) {
#pragma unroll
        for (int ni = 0; ni < 4; ni++) {
            const int ch = m0 + wn * 32 + ni * 8 + lc;
            float b0 = 0.f, b1 = 0.f;
            if (MODE != 3) { b0 = __ldg(bias + ch); b1 = __ldg(bias + ch + 1); }
#pragma unroll
            for (int hh = 0; hh < 2; hh++) {
                const int pix = n0 + wm * 32 + mi * 16 + lr + hh * 8;
                const size_t prow = (size_t)b * HWSZ + pix;
                float v0 = acc[mi][ni][hh * 2] * INVWS + b0;
                float v1 = acc[mi][ni][hh * 2 + 1] * INVWS + b1;
                float2 vv; vv.x = v0; vv.y = v1;
                *(float2*)(outf + prow * (size_t)Mtot + ch) = vv;
                if (MODE == 0) {
                    size_t o = prow * 512 + ch;
                    *(__half2*)(oh + o) = __halves2half2(__float2half(v0), __float2half(v1));
                }
            }
        }
    }
}

// ---------------- attention scores ----------------
__global__ __launch_bounds__(256)
void scores_kernel(const float* __restrict__ qkv, float* __restrict__ attn) {
    extern __shared__ float sm[];
    float* Qs = sm;
    float* Ks = sm + 96 * 64;
    const int fix = blockIdx.x, dir = blockIdx.y, b = blockIdx.z;
    const int tid = threadIdx.x;
    for (int idx = tid; idx < 96 * 32; idx += 256) {
        int p = idx >> 5, f = idx & 31;
        size_t row = (size_t)b * HWSZ + (dir == 0 ? p * IMG + fix : fix * IMG + p);
        float4 v = *(const float4*)&qkv[row * 640 + f * 4];
        if (f < 16) *(float4*)&Qs[p * 64 + f * 4] = v;
        else        *(float4*)&Ks[p * 68 + (f - 16) * 4] = v;
    }
    __syncthreads();
    for (int idx = tid; idx < 9216; idx += 256) {
        int p = idx / 96, r = idx - p * 96;
        const float* qp = &Qs[p * 64];
        const float* kp = &Ks[r * 68];
        float a0 = 0.f, a1 = 0.f, a2 = 0.f, a3 = 0.f;
#pragma unroll
        for (int t = 0; t < 16; t++) {
            float4 a = *(const float4*)&qp[t * 4];
            float4 k = *(const float4*)&kp[t * 4];
            a0 += a.x * k.x; a1 += a.y * k.y; a2 += a.z * k.z; a3 += a.w * k.w;
        }
        float val = (a0 + a1) + (a2 + a3);
        if (dir == 0 && r == p) val = -1e30f;
        size_t o = (dir == 0)
            ? ((size_t)b * HWSZ + p * IMG + fix) * 192 + r
            : ((size_t)b * HWSZ + fix * IMG + p) * 192 + 96 + r;
        attn[o] = val;
    }
}

__global__ __launch_bounds__(256)
void softmax_kernel(float* __restrict__ attn) {
    const int warp = threadIdx.x >> 5, lane = threadIdx.x & 31;
    const int pix = blockIdx.x * 8 + warp;
    float* p = attn + (size_t)pix * 192;
    float v[6];
#pragma unroll
    for (int t = 0; t < 6; t++) v[t] = p[lane + 32 * t];
    float m = v[0];
#pragma unroll
    for (int t = 1; t < 6; t++) m = fmaxf(m, v[t]);
#pragma unroll
    for (int off = 16; off > 0; off >>= 1) m = fmaxf(m, __shfl_xor_sync(0xffffffffu, m, off));
    float s = 0.f;
#pragma unroll
    for (int t = 0; t < 6; t++) { v[t] = __expf(v[t] - m); s += v[t]; }
#pragma unroll
    for (int off = 16; off > 0; off >>= 1) s += __shfl_xor_sync(0xffffffffu, s, off);
    float inv = 1.f / s;
#pragma unroll
    for (int t = 0; t < 6; t++) p[lane + 32 * t] = v[t] * inv;
}

// ---------------- aggregation via tensor cores (V single fp16) ------------
#define AG_SMEM 46592
template <int DIR>
__global__ __launch_bounds__(256, 2)
void agg_mma(const float* __restrict__ qkv, const float* __restrict__ attn,
             float* __restrict__ accb, const float* __restrict__ zin,
             const float* __restrict__ gamma, float* __restrict__ zout,
             f16* __restrict__ zh)
{
    extern __shared__ char smem[];
    f16* As = (f16*)smem;                       // [96][104]
    f16* Vh = (f16*)(smem + 19968);             // [128][104]
    const int fix = blockIdx.x, c0 = blockIdx.y * 128, b = blockIdx.z;
    const int tid = threadIdx.x, wid = tid >> 5, lane = tid & 31;

    for (int idx = tid; idx < 96 * 96; idx += 256) {
        int m = idx / 96, k = idx - m * 96;
        int pix = (DIR == 0) ? (m * IMG + fix) : (fix * IMG + m);
        As[m * 104 + k] = __float2half(attn[((size_t)b * HWSZ + pix) * 192 + DIR * 96 + k]);
    }
    for (int idx = tid; idx < 96 * 128; idx += 256) {
        int k = idx >> 7, c = idx & 127;
        int pix = (DIR == 0) ? (k * IMG + fix) : (fix * IMG + k);
        Vh[c * 104 + k] = __float2half(qkv[((size_t)b * HWSZ + pix) * 640 + 128 + c0 + c]);
    }
    __syncthreads();

    const uint32_t pA = s2u(As), pVh = s2u(Vh);
    const int mq = lane >> 3, rowin = lane & 7;
    const int lr = lane >> 2, lc = (lane & 3) * 2;

    float acc[6][2][4];
#pragma unroll
    for (int mi = 0; mi < 6; mi++)
#pragma unroll
        for (int ni = 0; ni < 2; ni++)
#pragma unroll
            for (int r = 0; r < 4; r++) acc[mi][ni][r] = 0.f;

#pragma unroll
    for (int ks = 0; ks < 6; ks++) {
        uint32_t a[6][4], bh[4];
        const int acol = ks * 16 + (mq >> 1) * 8;
#pragma unroll
        for (int mi = 0; mi < 6; mi++) {
            int row = mi * 16 + (mq & 1) * 8 + rowin;
            ldm_x4(a[mi], pA + (uint32_t)(row * 104 + acol) * 2);
        }
        {
            int n = wid * 16 + (mq >> 1) * 8 + rowin;
            int col = ks * 16 + (mq & 1) * 8;
            ldm_x4(bh, pVh + (uint32_t)(n * 104 + col) * 2);
        }
#pragma unroll
        for (int mi = 0; mi < 6; mi++) {
            mma16816(acc[mi][0], a[mi], bh);
            mma16816(acc[mi][1], a[mi], bh + 2);
        }
    }

    const float g = (DIR == 1) ? gamma[0] : 0.f;
#pragma unroll
    for (int mi = 0; mi < 6; mi++) {
#pragma unroll
        for (int ni = 0; ni < 2; ni++) {
            const int c = c0 + wid * 16 + ni * 8 + lc;
#pragma unroll
            for (int hh = 0; hh < 2; hh++) {
                const int m = mi * 16 + lr + hh * 8;
                const int pix = (DIR == 0) ? (m * IMG + fix) : (fix * IMG + m);
                const size_t o = ((size_t)b * HWSZ + pix) * 512 + c;
                float v0 = acc[mi][ni][hh * 2];
                float v1 = acc[mi][ni][hh * 2 + 1];
                if (DIR == 0) {
                    accb[o] = v0;
                    accb[o + 1] = v1;
                } else {
                    float w0 = g * (v0 + accb[o]) + zin[o];
                    float w1 = g * (v1 + accb[o + 1]) + zin[o + 1];
                    zout[o] = w0;
                    zout[o + 1] = w1;
                    *(__half2*)(zh + o) = __halves2half2(__float2half(w0), __float2half(w1));
                }
            }
        }
    }
}

// ---------------- GroupNorm ----------------
__global__ __launch_bounds__(256)
void gn_stats_cl(const float* __restrict__ x, float* __restrict__ stat) {
    const int b = blockIdx.x >> 5, gg = blockIdx.x & 31;
    const float* base = x + (size_t)b * HWSZ * 512 + gg * 16;
    float s = 0.f, ss = 0.f;
    for (int idx = threadIdx.x; idx < HWSZ * 4; idx += 256) {
        int pix = idx >> 2, q = idx & 3;
        float4 v = *(const float4*)(base + (size_t)pix * 512 + q * 4);
        s  += (v.x + v.y) + (v.z + v.w);
        ss += (v.x*v.x + v.y*v.y) + (v.z*v.z + v.w*v.w);
    }
    __shared__ float rs[8], rss[8];
    const int lane = threadIdx.x & 31, warp = threadIdx.x >> 5;
#pragma unroll
    for (int off = 16; off > 0; off >>= 1) {
        s  += __shfl_xor_sync(0xffffffffu, s, off);
        ss += __shfl_xor_sync(0xffffffffu, ss, off);
    }
    if (lane == 0) { rs[warp] = s; rss[warp] = ss; }
    __syncthreads();
    if (threadIdx.x == 0) {
        float S = 0.f, SS = 0.f;
#pragma unroll
        for (int i = 0; i < 8; i++) { S += rs[i]; SS += rss[i]; }
        float mean = S / 147456.f;
        float var = SS / 147456.f - mean * mean;
        stat[2 * blockIdx.x] = mean;
        stat[2 * blockIdx.x + 1] = rsqrtf(var + 1e-5f);
    }
}

__global__ __launch_bounds__(256)
void gn_out_kernel(const float* __restrict__ cl, const float* __restrict__ gam,
                   const float* __restrict__ bet, const float* __restrict__ stat,
                   float* __restrict__ out) {
    __shared__ float t[32][33];
    const int p0 = blockIdx.x * 32, c0 = blockIdx.y * 32, b = blockIdx.z;
    const int tx = threadIdx.x & 31, ty = threadIdx.x >> 5;
#pragma unroll
    for (int k = 0; k < 4; k++) {
        int pl = ty + k * 8;
        t[pl][tx] = cl[((size_t)b * HWSZ + p0 + pl) * 512 + c0 + tx];
    }
    __syncthreads();
#pragma unroll
    for (int k = 0; k < 4; k++) {
        int c = c0 + ty + k * 8;
        int sg = b * 32 + (c >> 4);
        float sc = stat[2 * sg + 1] * gam[c];
        float sh = bet[c] - stat[2 * sg] * sc;
        out[((size_t)b * 512 + c) * HWSZ + p0 + tx] = t[tx][ty + k * 8] * sc + sh;
    }
}

// ---------------- launch ----------------
extern "C" void kernel_launch(void* const* d_in, const int* in_sizes, int n_in,
                              void* d_out, int out_size) {
    const float* x   = (const float*)d_in[0];
    const float* c1w = (const float*)d_in[1];
    const float* c1b = (const float*)d_in[2];
    const float* qw  = (const float*)d_in[3];
    const float* qb  = (const float*)d_in[4];
    const float* kw  = (const float*)d_in[5];
    const float* kb  = (const float*)d_in[6];
    const float* vw  = (const float*)d_in[7];
    const float* vb  = (const float*)d_in[8];
    const float* gam = (const float*)d_in[9];
    const float* cow = (const float*)d_in[10];
    const float* gng = (const float*)d_in[11];
    const float* gnb = (const float*)d_in[12];
    float* out = (float*)d_out;

    void *p;
#define SYM(var, sym) cudaGetSymbolAddress(&p, sym); auto* var = (decltype(&sym[0]))p;
    SYM(xh, g_xh) SYM(zh, g_zh)
    SYM(z, g_z) SYM(z2, g_z2) SYM(qkv, g_qkv)
    SYM(attn, g_attn) SYM(acc, g_acc) SYM(cl, g_cl)
    SYM(c1h, g_c1h) SYM(qvh, g_qvh) SYM(qvl, g_qvl)
    SYM(w9h, g_w9h)
    SYM(bqv, g_bqv) SYM(st, g_stat)
#undef SYM

    const int SC_SM = 50688;
    cudaFuncSetAttribute(scores_kernel, cudaFuncAttributeMaxDynamicSharedMemorySize, SC_SM);
    cudaFuncSetAttribute(agg_mma<0>, cudaFuncAttributeMaxDynamicSharedMemorySize, AG_SMEM);
    cudaFuncSetAttribute(agg_mma<1>, cudaFuncAttributeMaxDynamicSharedMemorySize, AG_SMEM);
    cudaFuncSetAttribute(mma_gemm<0>, cudaFuncAttributeMaxDynamicSharedMemorySize, MG_SMEM);
    cudaFuncSetAttribute(mma_gemm<2>, cudaFuncAttributeMaxDynamicSharedMemorySize, MG_SMEM);
    cudaFuncSetAttribute(mma_gemm<3>, cudaFuncAttributeMaxDynamicSharedMemorySize, MG_SMEM);

    conv_x<<<dim3(288, 64, 2), 256>>>(x, xh);
    split_weights<<<(C1SZ + QVSZ + W9SZ + 255) / 256, 256>>>(
        c1w, qw, kw, vw, qb, kb, vb, cow, c1h, qvh, qvl, w9h, bqv);

    mma_gemm<0><<<dim3(72, 4, 2), 512, MG_SMEM>>>(xh, c1h, nullptr, c1b, z, zh, 2048, 512);

    for (int it = 0; it < 2; it++) {
        float* zi = it ? z2 : z;
        float* zo = it ? z : z2;
        mma_gemm<2><<<dim3(72, 5, 2), 512, MG_SMEM>>>(zh, qvh, qvl, bqv, qkv, nullptr, 512, 640);
        scores_kernel<<<dim3(96, 2, 2), 256, SC_SM>>>(qkv, attn);
        softmax_kernel<<<2304, 256>>>(attn);
        agg_mma<0><<<dim3(96, 4, 2), 256, AG_SMEM>>>(qkv, attn, acc, nullptr, nullptr, nullptr, nullptr);
        agg_mma<1><<<dim3(96, 4, 2), 256, AG_SMEM>>>(qkv, attn, acc, zi, gam, zo, zh);
    }

    mma_gemm<3><<<dim3(72, 4, 2), 512, MG_SMEM>>>(zh, w9h, nullptr, nullptr, cl, nullptr, 512, 512);
    gn_stats_cl<<<64, 256>>>(cl, st);
    gn_out_kernel<<<dim3(288, 16, 2), 256>>>(cl, gng, gnb, st, out);
}

// round 17
// speedup vs baseline: 2.0340x; 1.1148x over previous
#include <cuda_runtime.h>
#include <cuda_fp16.h>
#include <cstdint>

#define HWSZ 9216
#define IMG  96
typedef __half f16;

// ---------------- device scratch ----------------
__device__ f16 g_xh[2 * HWSZ * 2048];
__device__ f16 g_zh[2 * HWSZ * 512];
__device__ float g_z   [2 * HWSZ * 512];
__device__ float g_z2  [2 * HWSZ * 512];
__device__ float g_qkv [2 * HWSZ * 640];   // [q 0:64 | k 64:128 | v 128:640]
__device__ float g_attn[2 * HWSZ * 192];
__device__ float g_acc [2 * HWSZ * 512];
__device__ float g_cl  [2 * HWSZ * 512];
__device__ f16 g_c1h[512 * 2048];
__device__ f16 g_qvh[640 * 512],  g_qvl[640 * 512];
__device__ f16 g_w9h[9 * 512 * 512];
__device__ float g_bqv[640];
__device__ float g_stat[128];

#define WSCALE 64.0f
#define INVWS  0.015625f

// ---------------- helpers ----------------
__device__ __forceinline__ uint32_t s2u(const void* p) {
    uint32_t a;
    asm("{ .reg .u64 t; cvta.to.shared.u64 t, %1; cvt.u32.u64 %0, t; }" : "=r"(a) : "l"(p));
    return a;
}
__device__ __forceinline__ void hsplit(float v, f16* h, f16* l) {
    f16 hh = __float2half(v);
    *h = hh;
    *l = __float2half(v - __half2float(hh));
}
__device__ __forceinline__ void mma16816(float* d, const uint32_t* a, const uint32_t* b) {
    asm volatile(
        "mma.sync.aligned.m16n8k16.row.col.f32.f16.f16.f32 "
        "{%0,%1,%2,%3}, {%4,%5,%6,%7}, {%8,%9}, {%0,%1,%2,%3};"
        : "+f"(d[0]), "+f"(d[1]), "+f"(d[2]), "+f"(d[3])
        : "r"(a[0]), "r"(a[1]), "r"(a[2]), "r"(a[3]), "r"(b[0]), "r"(b[1]));
}
__device__ __forceinline__ void cpasync16(uint32_t s, const void* g) {
    asm volatile("cp.async.cg.shared.global [%0], [%1], 16;" :: "r"(s), "l"(g));
}
__device__ __forceinline__ void ldm_x4(uint32_t* r, uint32_t addr) {
    asm volatile("ldmatrix.sync.aligned.m8n8.x4.shared.b16 {%0,%1,%2,%3}, [%4];"
                 : "=r"(r[0]), "=r"(r[1]), "=r"(r[2]), "=r"(r[3]) : "r"(addr));
}

// ---------------- x -> fp16 channel-last ----------------
__global__ void conv_x(const float* __restrict__ x, f16* __restrict__ xh) {
    __shared__ float t[32][33];
    const int p0 = blockIdx.x * 32, c0 = blockIdx.y * 32, b = blockIdx.z;
    const int tx = threadIdx.x & 31, ty = threadIdx.x >> 5;
#pragma unroll
    for (int k = 0; k < 4; k++) {
        int cc = ty + k * 8;
        t[cc][tx] = x[((size_t)b * 2048 + c0 + cc) * HWSZ + p0 + tx];
    }
    __syncthreads();
#pragma unroll
    for (int k = 0; k < 4; k++) {
        int pl = ty + k * 8;
        size_t o = ((size_t)b * HWSZ + p0 + pl) * 2048 + c0 + tx;
        xh[o] = __float2half(t[tx][pl]);
    }
}

#define C1SZ  (512 * 2048)
#define QVSZ  (640 * 512)
#define W9SZ  (9 * 512 * 512)
__global__ void split_weights(const float* __restrict__ c1w,
                              const float* __restrict__ qw, const float* __restrict__ kw,
                              const float* __restrict__ vw, const float* __restrict__ qb,
                              const float* __restrict__ kb, const float* __restrict__ vb,
                              const float* __restrict__ cow,
                              f16* __restrict__ c1h,
                              f16* __restrict__ qvh, f16* __restrict__ qvl,
                              f16* __restrict__ w9h,
                              float* __restrict__ bqv) {
    int i = blockIdx.x * 256 + threadIdx.x;
    if (i < 640)
        bqv[i] = (i < 64) ? qb[i] : (i < 128) ? kb[i - 64] : vb[i - 128];
    if (i < C1SZ) {
        c1h[i] = __float2half(WSCALE * c1w[i]);
    } else if (i < C1SZ + QVSZ) {
        int j = i - C1SZ;
        int m = j >> 9, k = j & 511;
        float v = (m < 64) ? qw[m * 512 + k]
                : (m < 128) ? kw[(m - 64) * 512 + k]
                            : vw[(m - 128) * 512 + k];
        hsplit(WSCALE * v, &qvh[j], &qvl[j]);
    } else if (i < C1SZ + QVSZ + W9SZ) {
        int d = i - C1SZ - QVSZ;
        int s = d / (512 * 512), r = d % (512 * 512);
        int o = r >> 9, ic = r & 511;
        w9h[d] = __float2half(WSCALE * cow[(o * 512 + ic) * 9 + s]);
    }
}

// ---------------- fp16 tensor-core GEMM, BK=64 ----------------
// D = (1/64)*(A . (64B)^T) + bias
// TERMS = 2 (MODE 2: qkv, B split hi/lo) or 1 (MODE 0 conv1 / MODE 3 conv3)
#define OPSZ 9216            // 128 rows x 72 elems
#define OPB  18432
#define BUFE 27648           // 3 operands per stage
#define BUFB 55296
#define NSTG 3
#define MG_SMEM (4864 + NSTG * BUFB)
template <int MODE>
__global__ __launch_bounds__(512, 1)
void mma_gemm(const f16* __restrict__ A, const f16* __restrict__ Bh,
              const f16* __restrict__ Bl, const float* __restrict__ bias,
              float* __restrict__ outf, f16* __restrict__ oh,
              int K, int Mtot)
{
    constexpr int TERMS = (MODE == 2) ? 2 : 1;
    extern __shared__ char smem[];
    int* srcn = (int*)smem;
    f16* tiles = (f16*)(smem + 4864);
    const uint32_t smbase = s2u(tiles);
    const int tid = threadIdx.x, wid = tid >> 5, lane = tid & 31;
    const int n0 = blockIdx.x * 128, m0 = blockIdx.y * 128, b = blockIdx.z;

    if (MODE == 3 && tid < 128) {
        int n = n0 + tid, y = n / IMG, x = n - y * IMG;
#pragma unroll
        for (int s = 0; s < 9; s++) {
            int sy = y + s / 3 - 1, sx = x + s % 3 - 1;
            srcn[s * 128 + tid] = (sy >= 0 && sy < IMG && sx >= 0 && sx < IMG) ? sy * IMG + sx : -1;
        }
    }
    __syncthreads();

    // loaders: g<2 (256 thr) -> A ; g==2 -> Bh ; g==3 -> Bl (idle if TERMS==1)
    const int g = tid >> 7, u = tid & 127;
    const int nch = (MODE == 3) ? 72 : (K >> 6);

    auto load_chunk = [&](int i) {
        f16* t = tiles + (i % NSTG) * BUFE;
        int s = 0, k0;
        if (MODE == 3) { s = i >> 3; k0 = (i & 7) << 6; } else { k0 = i << 6; }
        if (g < 2) {
            const int tt = (g << 7) | u, qq = tt & 7, rr = tt >> 3;  // 8 segs, 32 rows
#pragma unroll
            for (int j = 0; j < 4; j++) {
                int row = rr + j * 32;
                uint32_t sa = s2u(t + row * 72 + qq * 8);
                long rn = -1;
                if (MODE == 3) { int sn = srcn[s * 128 + row]; if (sn >= 0) rn = sn; }
                else rn = n0 + row;
                if (rn >= 0)
                    cpasync16(sa, A + ((size_t)b * HWSZ + rn) * (size_t)K + k0 + qq * 8);
                else
                    *(uint4*)(t + row * 72 + qq * 8) = make_uint4(0, 0, 0, 0);
            }
        } else if (g == 2 || TERMS == 2) {
            const f16* srcp = (g == 2) ? Bh : Bl;
            f16* td = t + (g - 1) * OPSZ;
            const int qq = u & 7, rr = u >> 3;   // 8 segs, 16 rows
#pragma unroll
            for (int j = 0; j < 8; j++) {
                int row = rr + j * 16;
                uint32_t sa = s2u(td + row * 72 + qq * 8);
                size_t mrow = (MODE == 3) ? ((size_t)s * 512 + m0 + row) : (size_t)(m0 + row);
                cpasync16(sa, srcp + mrow * (size_t)K + k0 + qq * 8);
            }
        }
        asm volatile("cp.async.commit_group;" ::: "memory");
    };

    float acc[2][4][4];
#pragma unroll
    for (int mi = 0; mi < 2; mi++)
#pragma unroll
        for (int ni = 0; ni < 4; ni++)
#pragma unroll
            for (int r = 0; r < 4; r++) acc[mi][ni][r] = 0.f;

    const int wm = wid >> 2, wn = wid & 3;
    const int lr = lane >> 2, lc = (lane & 3) * 2;
    const int mq = lane >> 3, rowin = lane & 7;

    uint32_t aoff[4][2], boff[4][2];
#pragma unroll
    for (int ks = 0; ks < 4; ks++) {
#pragma unroll
        for (int mi = 0; mi < 2; mi++) {
            int row = wm * 32 + mi * 16 + (mq & 1) * 8 + rowin;
            int col = ks * 16 + (mq >> 1) * 8;
            aoff[ks][mi] = (uint32_t)(row * 72 + col) * 2;
        }
#pragma unroll
        for (int np = 0; np < 2; np++) {
            int n = wn * 32 + np * 16 + (mq >> 1) * 8 + rowin;
            int col = ks * 16 + (mq & 1) * 8;
            boff[ks][np] = (uint32_t)(n * 72 + col) * 2;
        }
    }

    load_chunk(0);
    if (nch > 1) load_chunk(1);
    asm volatile("cp.async.wait_group %0;" :: "n"(1) : "memory");
    __syncthreads();

    for (int i = 0; i < nch; i++) {
        if (i + 2 < nch) load_chunk(i + 2);
        const uint32_t tb = smbase + (i % NSTG) * BUFB;
        const uint32_t pA = tb, pBh = tb + OPB, pBl = tb + 2 * OPB;
#pragma unroll
        for (int ks = 0; ks < 4; ks++) {
            uint32_t ah[2][4], bh[4][2], bl[4][2], tmp[4];
#pragma unroll
            for (int mi = 0; mi < 2; mi++)
                ldm_x4(ah[mi], pA + aoff[ks][mi]);
#pragma unroll
            for (int np = 0; np < 2; np++) {
                ldm_x4(tmp, pBh + boff[ks][np]);
                bh[2*np][0] = tmp[0]; bh[2*np][1] = tmp[1];
                bh[2*np+1][0] = tmp[2]; bh[2*np+1][1] = tmp[3];
                if (TERMS == 2) {
                    ldm_x4(tmp, pBl + boff[ks][np]);
                    bl[2*np][0] = tmp[0]; bl[2*np][1] = tmp[1];
                    bl[2*np+1][0] = tmp[2]; bl[2*np+1][1] = tmp[3];
                }
            }
#pragma unroll
            for (int mi = 0; mi < 2; mi++)
#pragma unroll
                for (int ni = 0; ni < 4; ni++)
                    mma16816(acc[mi][ni], ah[mi], bh[ni]);
            if (TERMS == 2) {
#pragma unroll
                for (int mi = 0; mi < 2; mi++)
#pragma unroll
                    for (int ni = 0; ni < 4; ni++)
                        mma16816(acc[mi][ni], ah[mi], bl[ni]);
            }
        }
        if (i + 1 < nch) {
            if (i + 2 < nch)
                asm volatile("cp.async.wait_group %0;" :: "n"(1) : "memory");
            else
                asm volatile("cp.async.wait_group %0;" :: "n"(0) : "memory");
            __syncthreads();
        }
    }

#pragma unroll
    for (int mi = 0; mi < 2; mi++) {
#pragma unroll
        for (int ni = 0; ni < 4; ni++) {
            const int ch = m0 + wn * 32 + ni * 8 + lc;
            float b0 = 0.f, b1 = 0.f;
            if (MODE != 3) { b0 = __ldg(bias + ch); b1 = __ldg(bias + ch + 1); }
#pragma unroll
            for (int hh = 0; hh < 2; hh++) {
                const int pix = n0 + wm * 32 + mi * 16 + lr + hh * 8;
                const size_t prow = (size_t)b * HWSZ + pix;
                float v0 = acc[mi][ni][hh * 2] * INVWS + b0;
                float v1 = acc[mi][ni][hh * 2 + 1] * INVWS + b1;
                float2 vv; vv.x = v0; vv.y = v1;
                *(float2*)(outf + prow * (size_t)Mtot + ch) = vv;
                if (MODE == 0) {
                    size_t o = prow * 512 + ch;
                    *(__half2*)(oh + o) = __halves2half2(__float2half(v0), __float2half(v1));
                }
            }
        }
    }
}

// ---------------- attention scores ----------------
__global__ __launch_bounds__(256)
void scores_kernel(const float* __restrict__ qkv, float* __restrict__ attn) {
    extern __shared__ float sm[];
    float* Qs = sm;
    float* Ks = sm + 96 * 64;
    const int fix = blockIdx.x, dir = blockIdx.y, b = blockIdx.z;
    const int tid = threadIdx.x;
    for (int idx = tid; idx < 96 * 32; idx += 256) {
        int p = idx >> 5, f = idx & 31;
        size_t row = (size_t)b * HWSZ + (dir == 0 ? p * IMG + fix : fix * IMG + p);
        float4 v = *(const float4*)&qkv[row * 640 + f * 4];
        if (f < 16) *(float4*)&Qs[p * 64 + f * 4] = v;
        else        *(float4*)&Ks[p * 68 + (f - 16) * 4] = v;
    }
    __syncthreads();
    for (int idx = tid; idx < 9216; idx += 256) {
        int p = idx / 96, r = idx - p * 96;
        const float* qp = &Qs[p * 64];
        const float* kp = &Ks[r * 68];
        float a0 = 0.f, a1 = 0.f, a2 = 0.f, a3 = 0.f;
#pragma unroll
        for (int t = 0; t < 16; t++) {
            float4 a = *(const float4*)&qp[t * 4];
            float4 k = *(const float4*)&kp[t * 4];
            a0 += a.x * k.x; a1 += a.y * k.y; a2 += a.z * k.z; a3 += a.w * k.w;
        }
        float val = (a0 + a1) + (a2 + a3);
        if (dir == 0 && r == p) val = -1e30f;
        size_t o = (dir == 0)
            ? ((size_t)b * HWSZ + p * IMG + fix) * 192 + r
            : ((size_t)b * HWSZ + fix * IMG + p) * 192 + 96 + r;
        attn[o] = val;
    }
}

__global__ __launch_bounds__(256)
void softmax_kernel(float* __restrict__ attn) {
    const int warp = threadIdx.x >> 5, lane = threadIdx.x & 31;
    const int pix = blockIdx.x * 8 + warp;
    float* p = attn + (size_t)pix * 192;
    float v[6];
#pragma unroll
    for (int t = 0; t < 6; t++) v[t] = p[lane + 32 * t];
    float m = v[0];
#pragma unroll
    for (int t = 1; t < 6; t++) m = fmaxf(m, v[t]);
#pragma unroll
    for (int off = 16; off > 0; off >>= 1) m = fmaxf(m, __shfl_xor_sync(0xffffffffu, m, off));
    float s = 0.f;
#pragma unroll
    for (int t = 0; t < 6; t++) { v[t] = __expf(v[t] - m); s += v[t]; }
#pragma unroll
    for (int off = 16; off > 0; off >>= 1) s += __shfl_xor_sync(0xffffffffu, s, off);
    float inv = 1.f / s;
#pragma unroll
    for (int t = 0; t < 6; t++) p[lane + 32 * t] = v[t] * inv;
}

// ---------------- aggregation via tensor cores (V single fp16) ------------
#define AG_SMEM 46592
template <int DIR>
__global__ __launch_bounds__(256, 2)
void agg_mma(const float* __restrict__ qkv, const float* __restrict__ attn,
             float* __restrict__ accb, const float* __restrict__ zin,
             const float* __restrict__ gamma, float* __restrict__ zout,
             f16* __restrict__ zh)
{
    extern __shared__ char smem[];
    f16* As = (f16*)smem;                       // [96][104]
    f16* Vh = (f16*)(smem + 19968);             // [128][104]
    const int fix = blockIdx.x, c0 = blockIdx.y * 128, b = blockIdx.z;
    const int tid = threadIdx.x, wid = tid >> 5, lane = tid & 31;

    for (int idx = tid; idx < 96 * 96; idx += 256) {
        int m = idx / 96, k = idx - m * 96;
        int pix = (DIR == 0) ? (m * IMG + fix) : (fix * IMG + m);
        As[m * 104 + k] = __float2half(attn[((size_t)b * HWSZ + pix) * 192 + DIR * 96 + k]);
    }
    for (int idx = tid; idx < 96 * 128; idx += 256) {
        int k = idx >> 7, c = idx & 127;
        int pix = (DIR == 0) ? (k * IMG + fix) : (fix * IMG + k);
        Vh[c * 104 + k] = __float2half(qkv[((size_t)b * HWSZ + pix) * 640 + 128 + c0 + c]);
    }
    __syncthreads();

    const uint32_t pA = s2u(As), pVh = s2u(Vh);
    const int mq = lane >> 3, rowin = lane & 7;
    const int lr = lane >> 2, lc = (lane & 3) * 2;

    float acc[6][2][4];
#pragma unroll
    for (int mi = 0; mi < 6; mi++)
#pragma unroll
        for (int ni = 0; ni < 2; ni++)
#pragma unroll
            for (int r = 0; r < 4; r++) acc[mi][ni][r] = 0.f;

#pragma unroll
    for (int ks = 0; ks < 6; ks++) {
        uint32_t a[6][4], bh[4];
        const int acol = ks * 16 + (mq >> 1) * 8;
#pragma unroll
        for (int mi = 0; mi < 6; mi++) {
            int row = mi * 16 + (mq & 1) * 8 + rowin;
            ldm_x4(a[mi], pA + (uint32_t)(row * 104 + acol) * 2);
        }
        {
            int n = wid * 16 + (mq >> 1) * 8 + rowin;
            int col = ks * 16 + (mq & 1) * 8;
            ldm_x4(bh, pVh + (uint32_t)(n * 104 + col) * 2);
        }
#pragma unroll
        for (int mi = 0; mi < 6; mi++) {
            mma16816(acc[mi][0], a[mi], bh);
            mma16816(acc[mi][1], a[mi], bh + 2);
        }
    }

    const float g = (DIR == 1) ? gamma[0] : 0.f;
#pragma unroll
    for (int mi = 0; mi < 6; mi++) {
#pragma unroll
        for (int ni = 0; ni < 2; ni++) {
            const int c = c0 + wid * 16 + ni * 8 + lc;
#pragma unroll
            for (int hh = 0; hh < 2; hh++) {
                const int m = mi * 16 + lr + hh * 8;
                const int pix = (DIR == 0) ? (m * IMG + fix) : (fix * IMG + m);
                const size_t o = ((size_t)b * HWSZ + pix) * 512 + c;
                float v0 = acc[mi][ni][hh * 2];
                float v1 = acc[mi][ni][hh * 2 + 1];
                if (DIR == 0) {
                    accb[o] = v0;
                    accb[o + 1] = v1;
                } else {
                    float w0 = g * (v0 + accb[o]) + zin[o];
                    float w1 = g * (v1 + accb[o + 1]) + zin[o + 1];
                    zout[o] = w0;
                    zout[o + 1] = w1;
                    *(__half2*)(zh + o) = __halves2half2(__float2half(w0), __float2half(w1));
                }
            }
        }
    }
}

// ---------------- GroupNorm ----------------
__global__ __launch_bounds__(256)
void gn_stats_cl(const float* __restrict__ x, float* __restrict__ stat) {
    const int b = blockIdx.x >> 5, gg = blockIdx.x & 31;
    const float* base = x + (size_t)b * HWSZ * 512 + gg * 16;
    float s = 0.f, ss = 0.f;
    for (int idx = threadIdx.x; idx < HWSZ * 4; idx += 256) {
        int pix = idx >> 2, q = idx & 3;
        float4 v = *(const float4*)(base + (size_t)pix * 512 + q * 4);
        s  += (v.x + v.y) + (v.z + v.w);
        ss += (v.x*v.x + v.y*v.y) + (v.z*v.z + v.w*v.w);
    }
    __shared__ float rs[8], rss[8];
    const int lane = threadIdx.x & 31, warp = threadIdx.x >> 5;
#pragma unroll
    for (int off = 16; off > 0; off >>= 1) {
        s  += __shfl_xor_sync(0xffffffffu, s, off);
        ss += __shfl_xor_sync(0xffffffffu, ss, off);
    }
    if (lane == 0) { rs[warp] = s; rss[warp] = ss; }
    __syncthreads();
    if (threadIdx.x == 0) {
        float S = 0.f, SS = 0.f;
#pragma unroll
        for (int i = 0; i < 8; i++) { S += rs[i]; SS += rss[i]; }
        float mean = S / 147456.f;
        float var = SS / 147456.f - mean * mean;
        stat[2 * blockIdx.x] = mean;
        stat[2 * blockIdx.x + 1] = rsqrtf(var + 1e-5f);
    }
}

__global__ __launch_bounds__(256)
void gn_out_kernel(const float* __restrict__ cl, const float* __restrict__ gam,
                   const float* __restrict__ bet, const float* __restrict__ stat,
                   float* __restrict__ out) {
    __shared__ float t[32][33];
    const int p0 = blockIdx.x * 32, c0 = blockIdx.y * 32, b = blockIdx.z;
    const int tx = threadIdx.x & 31, ty = threadIdx.x >> 5;
#pragma unroll
    for (int k = 0; k < 4; k++) {
        int pl = ty + k * 8;
        t[pl][tx] = cl[((size_t)b * HWSZ + p0 + pl) * 512 + c0 + tx];
    }
    __syncthreads();
#pragma unroll
    for (int k = 0; k < 4; k++) {
        int c = c0 + ty + k * 8;
        int sg = b * 32 + (c >> 4);
        float sc = stat[2 * sg + 1] * gam[c];
        float sh = bet[c] - stat[2 * sg] * sc;
        out[((size_t)b * 512 + c) * HWSZ + p0 + tx] = t[tx][ty + k * 8] * sc + sh;
    }
}

// ---------------- launch ----------------
extern "C" void kernel_launch(void* const* d_in, const int* in_sizes, int n_in,
                              void* d_out, int out_size) {
    const float* x   = (const float*)d_in[0];
    const float* c1w = (const float*)d_in[1];
    const float* c1b = (const float*)d_in[2];
    const float* qw  = (const float*)d_in[3];
    const float* qb  = (const float*)d_in[4];
    const float* kw  = (const float*)d_in[5];
    const float* kb  = (const float*)d_in[6];
    const float* vw  = (const float*)d_in[7];
    const float* vb  = (const float*)d_in[8];
    const float* gam = (const float*)d_in[9];
    const float* cow = (const float*)d_in[10];
    const float* gng = (const float*)d_in[11];
    const float* gnb = (const float*)d_in[12];
    float* out = (float*)d_out;

    void *p;
#define SYM(var, sym) cudaGetSymbolAddress(&p, sym); auto* var = (decltype(&sym[0]))p;
    SYM(xh, g_xh) SYM(zh, g_zh)
    SYM(z, g_z) SYM(z2, g_z2) SYM(qkv, g_qkv)
    SYM(attn, g_attn) SYM(acc, g_acc) SYM(cl, g_cl)
    SYM(c1h, g_c1h) SYM(qvh, g_qvh) SYM(qvl, g_qvl)
    SYM(w9h, g_w9h)
    SYM(bqv, g_bqv) SYM(st, g_stat)
#undef SYM

    const int SC_SM = 50688;
    cudaFuncSetAttribute(scores_kernel, cudaFuncAttributeMaxDynamicSharedMemorySize, SC_SM);
    cudaFuncSetAttribute(agg_mma<0>, cudaFuncAttributeMaxDynamicSharedMemorySize, AG_SMEM);
    cudaFuncSetAttribute(agg_mma<1>, cudaFuncAttributeMaxDynamicSharedMemorySize, AG_SMEM);
    cudaFuncSetAttribute(mma_gemm<0>, cudaFuncAttributeMaxDynamicSharedMemorySize, MG_SMEM);
    cudaFuncSetAttribute(mma_gemm<2>, cudaFuncAttributeMaxDynamicSharedMemorySize, MG_SMEM);
    cudaFuncSetAttribute(mma_gemm<3>, cudaFuncAttributeMaxDynamicSharedMemorySize, MG_SMEM);

    conv_x<<<dim3(288, 64, 2), 256>>>(x, xh);
    split_weights<<<(C1SZ + QVSZ + W9SZ + 255) / 256, 256>>>(
        c1w, qw, kw, vw, qb, kb, vb, cow, c1h, qvh, qvl, w9h, bqv);

    mma_gemm<0><<<dim3(72, 4, 2), 512, MG_SMEM>>>(xh, c1h, nullptr, c1b, z, zh, 2048, 512);

    for (int it = 0; it < 2; it++) {
        float* zi = it ? z2 : z;
        float* zo = it ? z : z2;
        mma_gemm<2><<<dim3(72, 5, 2), 512, MG_SMEM>>>(zh, qvh, qvl, bqv, qkv, nullptr, 512, 640);
        scores_kernel<<<dim3(96, 2, 2), 256, SC_SM>>>(qkv, attn);
        softmax_kernel<<<2304, 256>>>(attn);
        agg_mma<0><<<dim3(96, 4, 2), 256, AG_SMEM>>>(qkv, attn, acc, nullptr, nullptr, nullptr, nullptr);
        agg_mma<1><<<dim3(96, 4, 2), 256, AG_SMEM>>>(qkv, attn, acc, zi, gam, zo, zh);
    }

    mma_gemm<3><<<dim3(72, 4, 2), 512, MG_SMEM>>>(zh, w9h, nullptr, nullptr, cl, nullptr, 512, 512);
    gn_stats_cl<<<64, 256>>>(cl, st);
    gn_out_kernel<<<dim3(288, 16, 2), 256>>>(cl, gng, gnb, st, out);
}